// round 13
// baseline (speedup 1.0000x reference)
#include <cuda_runtime.h>
#include <cuda_bf16.h>
#include <cstdint>

#define TOKENS 8192
#define DM     1024
#define LSEQ   2048
#define NB     4
#define NH     16
#define DK     64

// Scratch (device globals — no allocation in kernel_launch)
__device__ float g_qkv[(size_t)TOKENS * 3 * DM]; // qkv fp32 (gemm out)
__device__ __nv_bfloat16 g_hh[TOKENS * DM];      // layernorm out hi
__device__ __nv_bfloat16 g_hl[TOKENS * DM];      // layernorm out lo
__device__ __nv_bfloat16 g_wih[3 * DM * DM];     // W_in hi
__device__ __nv_bfloat16 g_wil[3 * DM * DM];     // W_in lo
__device__ __nv_bfloat16 g_woh[DM * DM];         // W_o hi
__device__ __nv_bfloat16 g_wol[DM * DM];         // W_o lo
__device__ __nv_bfloat16 g_oh[TOKENS * DM];      // attention out hi
__device__ __nv_bfloat16 g_ol[TOKENS * DM];      // attention out lo
// pre-split roped q/k and v for flash
__device__ __nv_bfloat16 g_qh[TOKENS * DM], g_ql[TOKENS * DM];
__device__ __nv_bfloat16 g_kh[TOKENS * DM], g_kl[TOKENS * DM];
__device__ __nv_bfloat16 g_vh[TOKENS * DM], g_vl[TOKENS * DM];

// ===========================================================================
// Helpers
// ===========================================================================
__device__ __forceinline__ void mma_bf16(float* c, const uint32_t* a,
                                         const uint32_t* b) {
    asm volatile(
        "mma.sync.aligned.m16n8k16.row.col.f32.bf16.bf16.f32 "
        "{%0,%1,%2,%3}, {%4,%5,%6,%7}, {%8,%9}, {%0,%1,%2,%3};\n"
        : "+f"(c[0]), "+f"(c[1]), "+f"(c[2]), "+f"(c[3])
        : "r"(a[0]), "r"(a[1]), "r"(a[2]), "r"(a[3]), "r"(b[0]), "r"(b[1]));
}
__device__ __forceinline__ uint32_t pack2(__nv_bfloat16 lo, __nv_bfloat16 hi) {
    __nv_bfloat162 t = __halves2bfloat162(lo, hi);
    return *reinterpret_cast<uint32_t*>(&t);
}
__device__ __forceinline__ uint32_t smem_u32addr(const void* p) {
    uint32_t a;
    asm("{ .reg .u64 t; cvta.to.shared.u64 t, %1; cvt.u32.u64 %0, t; }"
        : "=r"(a) : "l"(p));
    return a;
}
__device__ __forceinline__ void ldmx4(uint32_t& r0, uint32_t& r1,
                                      uint32_t& r2, uint32_t& r3,
                                      uint32_t addr) {
    asm volatile(
        "ldmatrix.sync.aligned.m8n8.x4.shared.b16 {%0,%1,%2,%3}, [%4];"
        : "=r"(r0), "=r"(r1), "=r"(r2), "=r"(r3) : "r"(addr));
}
__device__ __forceinline__ void ldmx4t(uint32_t& r0, uint32_t& r1,
                                       uint32_t& r2, uint32_t& r3,
                                       uint32_t addr) {
    asm volatile(
        "ldmatrix.sync.aligned.m8n8.x4.trans.shared.b16 {%0,%1,%2,%3}, [%4];"
        : "=r"(r0), "=r"(r1), "=r"(r2), "=r"(r3) : "r"(addr));
}
__device__ __forceinline__ void cp16(uint32_t dst, const void* src) {
    asm volatile("cp.async.cg.shared.global [%0], [%1], 16;"
                 :: "r"(dst), "l"(src) : "memory");
}
#define CP_COMMIT() asm volatile("cp.async.commit_group;" ::: "memory")
#define CP_WAIT0()  asm volatile("cp.async.wait_group 0;" ::: "memory")
#define CP_WAIT1()  asm volatile("cp.async.wait_group 1;" ::: "memory")

__device__ __forceinline__ void split4(float4 v, uint32_t& h0, uint32_t& h1,
                                       uint32_t& l0, uint32_t& l1) {
    __nv_bfloat16 hx = __float2bfloat16_rn(v.x);
    __nv_bfloat16 hy = __float2bfloat16_rn(v.y);
    __nv_bfloat16 hz = __float2bfloat16_rn(v.z);
    __nv_bfloat16 hw = __float2bfloat16_rn(v.w);
    h0 = pack2(hx, hy); h1 = pack2(hz, hw);
    l0 = pack2(__float2bfloat16_rn(v.x - __bfloat162float(hx)),
               __float2bfloat16_rn(v.y - __bfloat162float(hy)));
    l1 = pack2(__float2bfloat16_rn(v.z - __bfloat162float(hz)),
               __float2bfloat16_rn(v.w - __bfloat162float(hw)));
}
// split 2 floats -> (hi u32, lo u32)
__device__ __forceinline__ void split2(float a, float b, uint32_t& h, uint32_t& l) {
    __nv_bfloat16 ha = __float2bfloat16_rn(a);
    __nv_bfloat16 hb = __float2bfloat16_rn(b);
    h = pack2(ha, hb);
    l = pack2(__float2bfloat16_rn(a - __bfloat162float(ha)),
              __float2bfloat16_rn(b - __bfloat162float(hb)));
}

// ===========================================================================
// LayerNorm: one block per row, writes bf16 hi/lo split directly
// ===========================================================================
__global__ __launch_bounds__(256) void ln_kernel(const float* __restrict__ x,
                                                 __nv_bfloat16* __restrict__ hh,
                                                 __nv_bfloat16* __restrict__ hl) {
    int row = blockIdx.x;
    int t = threadIdx.x;
    const float4* xr = (const float4*)(x + (size_t)row * DM);
    float4 v = xr[t];
    float s  = v.x + v.y + v.z + v.w;
    float ss = v.x * v.x + v.y * v.y + v.z * v.z + v.w * v.w;
    #pragma unroll
    for (int off = 16; off; off >>= 1) {
        s  += __shfl_xor_sync(0xffffffffu, s, off);
        ss += __shfl_xor_sync(0xffffffffu, ss, off);
    }
    __shared__ float sh[16];
    __shared__ float sh_mu, sh_r;
    int warp = t >> 5, lane = t & 31;
    if (lane == 0) { sh[warp] = s; sh[warp + 8] = ss; }
    __syncthreads();
    if (t == 0) {
        float S = 0.f, SS = 0.f;
        #pragma unroll
        for (int w = 0; w < 8; w++) { S += sh[w]; SS += sh[w + 8]; }
        float mu  = S * (1.0f / DM);
        float var = SS * (1.0f / DM) - mu * mu;
        sh_mu = mu;
        sh_r  = rsqrtf(var + 1e-8f);
    }
    __syncthreads();
    float mu = sh_mu, r = sh_r;
    float4 o = make_float4((v.x - mu) * r, (v.y - mu) * r,
                           (v.z - mu) * r, (v.w - mu) * r);
    uint32_t h0, h1, l0, l1;
    split4(o, h0, h1, l0, l1);
    uint32_t* hw = (uint32_t*)(hh + (size_t)row * DM);
    uint32_t* lw = (uint32_t*)(hl + (size_t)row * DM);
    hw[2 * t] = h0; hw[2 * t + 1] = h1;
    lw[2 * t] = l0; lw[2 * t + 1] = l1;
}

// ===========================================================================
// Weight split: fp32 -> bf16 hi/lo
// ===========================================================================
__global__ __launch_bounds__(256) void split_kernel(const float* __restrict__ src,
                                                    __nv_bfloat16* __restrict__ hi,
                                                    __nv_bfloat16* __restrict__ lo,
                                                    int n4) {
    int i = blockIdx.x * blockDim.x + threadIdx.x;
    if (i >= n4) return;
    float4 v = ((const float4*)src)[i];
    uint32_t h0, h1, l0, l1;
    split4(v, h0, h1, l0, l1);
    ((uint32_t*)hi)[2 * i] = h0; ((uint32_t*)hi)[2 * i + 1] = h1;
    ((uint32_t*)lo)[2 * i] = l0; ((uint32_t*)lo)[2 * i + 1] = l1;
}

// ===========================================================================
// RoPE + split: read qkv fp32, apply rope to q,k, split q/k/v to bf16 hi/lo.
// Each element split exactly once.
// ===========================================================================
__global__ __launch_bounds__(512) void rope_split(const float* __restrict__ qkv,
        __nv_bfloat16* __restrict__ qh, __nv_bfloat16* __restrict__ ql,
        __nv_bfloat16* __restrict__ kh, __nv_bfloat16* __restrict__ kl,
        __nv_bfloat16* __restrict__ vh, __nv_bfloat16* __restrict__ vl) {
    int token = blockIdx.x;
    int p = threadIdx.x;
    int head = p >> 5;
    int i = p & 31;
    int l = token & (LSEQ - 1);
    double inv = pow(10000.0, -(double)i / 32.0);
    double ang = (double)l * inv;
    double snd, csd;
    sincos(ang, &snd, &csd);
    float sn = (float)snd, cs = (float)csd;
    size_t base = (size_t)token * 3 * DM + head * DK + 2 * i;
    size_t di = ((size_t)token * DM + head * DK + 2 * i) >> 1;  // u32 index
    uint32_t h, lo;
    // q
    float x1 = qkv[base], x2 = qkv[base + 1];
    split2(x1 * cs - x2 * sn, x1 * sn + x2 * cs, h, lo);
    ((uint32_t*)qh)[di] = h; ((uint32_t*)ql)[di] = lo;
    // k
    float y1 = qkv[base + DM], y2 = qkv[base + DM + 1];
    split2(y1 * cs - y2 * sn, y1 * sn + y2 * cs, h, lo);
    ((uint32_t*)kh)[di] = h; ((uint32_t*)kl)[di] = lo;
    // v (no rope)
    split2(qkv[base + 2 * DM], qkv[base + 2 * DM + 1], h, lo);
    ((uint32_t*)vh)[di] = h; ((uint32_t*)vl)[di] = lo;
}

// ===========================================================================
// Split-bf16 NT GEMM, pre-split bf16 inputs, 3-stage cp.async pipeline,
// 2 CTAs/SM, ldmatrix fragment loads.
// ===========================================================================
#define BM 128
#define BN 128
#define SROW 12
#define SARR (BM * SROW)              // 1536 u32
#define SSTAGE (4 * SARR)
#define GEMM_SMEM (3 * SSTAGE * 4)    // 73728 B

__global__ __launch_bounds__(256, 2) void gemm_bf(
    const __nv_bfloat16* __restrict__ Ah, const __nv_bfloat16* __restrict__ Al,
    const __nv_bfloat16* __restrict__ Bh, const __nv_bfloat16* __restrict__ Bl,
    float* __restrict__ C, int M, int N_, int K) {
    extern __shared__ uint32_t smu[];
    int t = threadIdx.x;
    int lane = t & 31, wid = t >> 5;
    int wm = wid >> 2, wn = wid & 3;
    int g = lane >> 2, t4 = lane & 3;
    int m0 = blockIdx.y * BM, n0 = blockIdx.x * BN;

    float acc[4][4][4];
    #pragma unroll
    for (int i = 0; i < 4; i++)
        #pragma unroll
        for (int j = 0; j < 4; j++)
            #pragma unroll
            for (int q = 0; q < 4; q++) acc[i][j][q] = 0.f;

    int lrow = t >> 1, lhalf = t & 1;
    uint32_t sbase = smem_u32addr(smu);
    uint32_t soff = (lrow * SROW + lhalf * 4) * 4;
    const __nv_bfloat16* ap  = Ah + (size_t)(m0 + lrow) * K + lhalf * 8;
    const __nv_bfloat16* alp = Al + (size_t)(m0 + lrow) * K + lhalf * 8;
    const __nv_bfloat16* bp  = Bh + (size_t)(n0 + lrow) * K + lhalf * 8;
    const __nv_bfloat16* blp = Bl + (size_t)(n0 + lrow) * K + lhalf * 8;

    const int NST = K / 16;
    // prologue: stages 0, 1
    #pragma unroll
    for (int s = 0; s < 2; s++) {
        uint32_t db = sbase + s * (SSTAGE * 4) + soff;
        int k0 = s * 16;
        cp16(db,                ap + k0);
        cp16(db + SARR * 4,     alp + k0);
        cp16(db + 2 * SARR * 4, bp + k0);
        cp16(db + 3 * SARR * 4, blp + k0);
        CP_COMMIT();
    }

    int r8 = lane & 7, mat = lane >> 3;
    int a_loff = ((wm * 64 + (mat & 1) * 8 + r8) * SROW + (mat >> 1) * 4) * 4;
    int b_loff = ((wn * 32 + (mat >> 1) * 8 + r8) * SROW + (mat & 1) * 4) * 4;

    int cur = 0;
    for (int s = 0; s < NST; s++) {
        CP_WAIT1();
        __syncthreads();
        if (s + 2 < NST) {
            int nxt = cur + 2; if (nxt >= 3) nxt -= 3;
            uint32_t db = sbase + nxt * (SSTAGE * 4) + soff;
            int k0 = (s + 2) * 16;
            cp16(db,                ap + k0);
            cp16(db + SARR * 4,     alp + k0);
            cp16(db + 2 * SARR * 4, bp + k0);
            cp16(db + 3 * SARR * 4, blp + k0);
            CP_COMMIT();
        } else {
            CP_COMMIT();   // keep group count in step for CP_WAIT1
        }

        uint32_t stb = sbase + cur * (SSTAGE * 4);
        uint32_t bh[4][2], bl[4][2];
        #pragma unroll
        for (int p = 0; p < 2; p++) {
            ldmx4(bh[2 * p][0], bh[2 * p][1], bh[2 * p + 1][0], bh[2 * p + 1][1],
                  stb + 2 * SARR * 4 + b_loff + p * (16 * SROW * 4));
            ldmx4(bl[2 * p][0], bl[2 * p][1], bl[2 * p + 1][0], bl[2 * p + 1][1],
                  stb + 3 * SARR * 4 + b_loff + p * (16 * SROW * 4));
        }
        #pragma unroll
        for (int mb = 0; mb < 4; mb++) {
            uint32_t ah[4], al[4];
            ldmx4(ah[0], ah[1], ah[2], ah[3],
                  stb + a_loff + mb * (16 * SROW * 4));
            ldmx4(al[0], al[1], al[2], al[3],
                  stb + SARR * 4 + a_loff + mb * (16 * SROW * 4));
            #pragma unroll
            for (int nb = 0; nb < 4; nb++) {
                mma_bf16(acc[mb][nb], ah, bh[nb]);
                mma_bf16(acc[mb][nb], ah, bl[nb]);
                mma_bf16(acc[mb][nb], al, bh[nb]);
            }
        }
        cur++; if (cur >= 3) cur -= 3;
    }

    #pragma unroll
    for (int mb = 0; mb < 4; mb++) {
        int row = m0 + wm * 64 + mb * 16 + g;
        #pragma unroll
        for (int nb = 0; nb < 4; nb++) {
            int col = n0 + wn * 32 + nb * 8 + 2 * t4;
            *(float2*)(C + (size_t)row * N_ + col) =
                make_float2(acc[mb][nb][0], acc[mb][nb][1]);
            *(float2*)(C + (size_t)(row + 8) * N_ + col) =
                make_float2(acc[mb][nb][2], acc[mb][nb][3]);
        }
    }
}

// ===========================================================================
// Tensor-core causal flash attention. Pre-split bf16 inputs, cp.async
// staging, double-buffered K/V tiles. Epilogue writes bf16 hi/lo.
// ===========================================================================
#define FQ 128
#define FK 64
#define FR 36                          // u32 row stride (144 B)
#define OQH 0
#define OQL (FQ * FR)                  // 4608
#define KV0 (2 * FQ * FR)              // 9216
#define SST (4 * FK * FR)              // 9216 u32 per stage
#define KH_O 0
#define KL_O (FK * FR)                 // 2304
#define VH_O (2 * FK * FR)
#define VL_O (3 * FK * FR)
#define FLASH_SMEM ((KV0 + 2 * SST) * 4)   // 110592 B

__global__ __launch_bounds__(256) void flash_tc(
        const __nv_bfloat16* __restrict__ qhp, const __nv_bfloat16* __restrict__ qlp,
        const __nv_bfloat16* __restrict__ khp, const __nv_bfloat16* __restrict__ klp,
        const __nv_bfloat16* __restrict__ vhp, const __nv_bfloat16* __restrict__ vlp,
        __nv_bfloat16* __restrict__ oh, __nv_bfloat16* __restrict__ ol) {
    extern __shared__ uint32_t su[];
    int t = threadIdx.x;
    int lane = t & 31, wq = t >> 5;
    int g = lane >> 2, t4 = lane & 3;
    int qt = (int)gridDim.x - 1 - (int)blockIdx.x;
    int h = blockIdx.y, b = blockIdx.z;
    int qbase = qt * FQ;
    uint32_t sbase = smem_u32addr(su);

    // ---- Q staging via cp.async (group 0) ----
    {
        size_t qoff = (size_t)(b * LSEQ + qbase) * DM + h * DK;
        #pragma unroll
        for (int it = 0; it < 4; it++) {
            int f = t + it * 256;           // 0..1023
            int row = f >> 3, c = f & 7;
            uint32_t d = sbase + row * 144 + c * 16;
            const __nv_bfloat16* s = qhp + qoff + (size_t)row * DM + c * 8;
            cp16(d, s);
            cp16(d + OQL * 4, qlp + qoff + (size_t)row * DM + c * 8);
        }
        CP_COMMIT();
    }
    // ---- K/V tile 0 staging (group 1) ----
    int nkt = 2 * qt + 2;
    {
        size_t koff = (size_t)(b * LSEQ) * DM + h * DK;
        #pragma unroll
        for (int it = 0; it < 2; it++) {
            int f = t + it * 256;           // 0..511
            int row = f >> 3, c = f & 7;
            uint32_t d = sbase + KV0 * 4 + row * 144 + c * 16;
            size_t s = koff + (size_t)row * DM + c * 8;
            cp16(d,            khp + s);
            cp16(d + KL_O * 4, klp + s);
            cp16(d + VH_O * 4, vhp + s);
            cp16(d + VL_O * 4, vlp + s);
        }
        CP_COMMIT();
    }
    CP_WAIT1();                 // Q done (tile 0 may still be in flight)
    __syncthreads();

    // ---- per-warp Q a-frags ----
    uint32_t qah[4][4], qal[4][4];
    #pragma unroll
    for (int s = 0; s < 4; s++) {
        int idx = (wq * 16 + g) * FR + 8 * s + t4;
        qah[s][0] = su[OQH + idx];          qah[s][1] = su[OQH + idx + 8 * FR];
        qah[s][2] = su[OQH + idx + 4];      qah[s][3] = su[OQH + idx + 8 * FR + 4];
        qal[s][0] = su[OQL + idx];          qal[s][1] = su[OQL + idx + 8 * FR];
        qal[s][2] = su[OQL + idx + 4];      qal[s][3] = su[OQL + idx + 8 * FR + 4];
    }

    float of[8][4];
    #pragma unroll
    for (int n = 0; n < 8; n++)
        #pragma unroll
        for (int c = 0; c < 4; c++) of[n][c] = 0.f;
    float m0 = -1e30f, m1 = -1e30f, l0 = 0.f, l1 = 0.f;

    int voff = ((lane & 15) * FR + (lane >> 4) * 4) * 4;
    int row0 = qbase + wq * 16 + g;

    for (int kt = 0; kt < nkt; kt++) {
        CP_WAIT0();             // tile kt staged
        __syncthreads();
        int st = kt & 1;
        // prefetch tile kt+1 into other buffer
        if (kt + 1 < nkt) {
            size_t koff = (size_t)(b * LSEQ + (kt + 1) * FK) * DM + h * DK;
            uint32_t dbase = sbase + (KV0 + (1 - st) * SST) * 4;
            #pragma unroll
            for (int it = 0; it < 2; it++) {
                int f = t + it * 256;
                int row = f >> 3, c = f & 7;
                uint32_t d = dbase + row * 144 + c * 16;
                size_t s = koff + (size_t)row * DM + c * 8;
                cp16(d,            khp + s);
                cp16(d + KL_O * 4, klp + s);
                cp16(d + VH_O * 4, vhp + s);
                cp16(d + VL_O * 4, vlp + s);
            }
        }
        CP_COMMIT();

        int ktb = kt * FK;
        bool active = (ktb <= qbase + wq * 16);
        if (active) {
            const uint32_t* stK = su + KV0 + st * SST;
            uint32_t vb_h = sbase + (KV0 + st * SST + VH_O) * 4;
            uint32_t vb_l = sbase + (KV0 + st * SST + VL_O) * 4;

            float sf[8][4];
            #pragma unroll
            for (int j = 0; j < 8; j++)
                #pragma unroll
                for (int c = 0; c < 4; c++) sf[j][c] = 0.f;
            #pragma unroll
            for (int s = 0; s < 4; s++) {
                #pragma unroll
                for (int j = 0; j < 8; j++) {
                    int idx = (8 * j + g) * FR + 8 * s + t4;
                    uint32_t kb2[2], kl2[2];
                    kb2[0] = stK[KH_O + idx]; kb2[1] = stK[KH_O + idx + 4];
                    kl2[0] = stK[KL_O + idx]; kl2[1] = stK[KL_O + idx + 4];
                    mma_bf16(sf[j], qah[s], kb2);
                    mma_bf16(sf[j], qal[s], kb2);
                    mma_bf16(sf[j], qah[s], kl2);
                }
            }

            const float scale = 0.125f;
            bool need_mask = (ktb + FK - 1 > qbase + wq * 16);
            #pragma unroll
            for (int j = 0; j < 8; j++) {
                int col = ktb + 8 * j + 2 * t4;
                #pragma unroll
                for (int c = 0; c < 4; c++) {
                    float v = sf[j][c] * scale;
                    if (need_mask) {
                        int cc = col + (c & 1);
                        int rr = row0 + (c >> 1) * 8;
                        if (cc > rr) v = -1e30f;
                    }
                    sf[j][c] = v;
                }
            }

            float mx0 = -1e30f, mx1 = -1e30f;
            #pragma unroll
            for (int j = 0; j < 8; j++) {
                mx0 = fmaxf(mx0, fmaxf(sf[j][0], sf[j][1]));
                mx1 = fmaxf(mx1, fmaxf(sf[j][2], sf[j][3]));
            }
            mx0 = fmaxf(mx0, __shfl_xor_sync(0xffffffffu, mx0, 1));
            mx0 = fmaxf(mx0, __shfl_xor_sync(0xffffffffu, mx0, 2));
            mx1 = fmaxf(mx1, __shfl_xor_sync(0xffffffffu, mx1, 1));
            mx1 = fmaxf(mx1, __shfl_xor_sync(0xffffffffu, mx1, 2));
            float mn0 = fmaxf(m0, mx0), mn1 = fmaxf(m1, mx1);
            float a0 = __expf(m0 - mn0), a1 = __expf(m1 - mn1);
            m0 = mn0; m1 = mn1;
            float s0 = 0.f, s1 = 0.f;
            #pragma unroll
            for (int j = 0; j < 8; j++) {
                sf[j][0] = __expf(sf[j][0] - m0);
                sf[j][1] = __expf(sf[j][1] - m0);
                sf[j][2] = __expf(sf[j][2] - m1);
                sf[j][3] = __expf(sf[j][3] - m1);
                s0 += sf[j][0] + sf[j][1];
                s1 += sf[j][2] + sf[j][3];
            }
            s0 += __shfl_xor_sync(0xffffffffu, s0, 1);
            s0 += __shfl_xor_sync(0xffffffffu, s0, 2);
            s1 += __shfl_xor_sync(0xffffffffu, s1, 1);
            s1 += __shfl_xor_sync(0xffffffffu, s1, 2);
            l0 = l0 * a0 + s0;
            l1 = l1 * a1 + s1;
            #pragma unroll
            for (int n = 0; n < 8; n++) {
                of[n][0] *= a0; of[n][1] *= a0;
                of[n][2] *= a1; of[n][3] *= a1;
            }

            #pragma unroll
            for (int s = 0; s < 4; s++) {
                uint32_t pah[4], pal[4];
                #pragma unroll
                for (int half = 0; half < 2; half++) {
                    float p0 = sf[2 * s + half][0], p1 = sf[2 * s + half][1];
                    float p2 = sf[2 * s + half][2], p3 = sf[2 * s + half][3];
                    split2(p0, p1, pah[2 * half], pal[2 * half]);
                    split2(p2, p3, pah[2 * half + 1], pal[2 * half + 1]);
                }
                #pragma unroll
                for (int j2 = 0; j2 < 4; j2++) {
                    uint32_t vh0, vh1, vh2, vh3, vl0, vl1, vl2, vl3;
                    uint32_t boff2 = (16 * s * FR + 8 * j2) * 4 + voff;
                    ldmx4t(vh0, vh1, vh2, vh3, vb_h + boff2);
                    ldmx4t(vl0, vl1, vl2, vl3, vb_l + boff2);
                    uint32_t bh0[2] = {vh0, vh1}, bh1[2] = {vh2, vh3};
                    uint32_t bl0[2] = {vl0, vl1}, bl1[2] = {vl2, vl3};
                    mma_bf16(of[2 * j2], pah, bh0);
                    mma_bf16(of[2 * j2], pal, bh0);
                    mma_bf16(of[2 * j2], pah, bl0);
                    mma_bf16(of[2 * j2 + 1], pah, bh1);
                    mma_bf16(of[2 * j2 + 1], pal, bh1);
                    mma_bf16(of[2 * j2 + 1], pah, bl1);
                }
            }
        }
        __syncthreads();
    }

    // ---- epilogue: write bf16 hi/lo split ----
    float i0 = 1.f / l0, i1 = 1.f / l1;
    size_t base0 = (size_t)(b * LSEQ + row0) * DM + h * DK;
    size_t base1 = base0 + 8 * DM;
    uint32_t* ohw = (uint32_t*)oh;
    uint32_t* olw = (uint32_t*)ol;
    #pragma unroll
    for (int n = 0; n < 8; n++) {
        int col = 8 * n + 2 * t4;
        uint32_t h0, l0w, h1, l1w;
        split2(of[n][0] * i0, of[n][1] * i0, h0, l0w);
        split2(of[n][2] * i1, of[n][3] * i1, h1, l1w);
        ohw[(base0 + col) >> 1] = h0;
        olw[(base0 + col) >> 1] = l0w;
        ohw[(base1 + col) >> 1] = h1;
        olw[(base1 + col) >> 1] = l1w;
    }
}

// ===========================================================================
extern "C" void kernel_launch(void* const* d_in, const int* in_sizes, int n_in,
                              void* d_out, int out_size) {
    const float* x    = (const float*)d_in[0];
    const float* W_in = (const float*)d_in[1];
    const float* W_o  = (const float*)d_in[2];
    float* out = (float*)d_out;

    float* qkv;
    __nv_bfloat16 *hh, *hl, *wih, *wil, *woh, *wol, *oh, *ol;
    __nv_bfloat16 *qh, *ql, *kh, *kl, *vh, *vl;
    cudaGetSymbolAddress((void**)&qkv, g_qkv);
    cudaGetSymbolAddress((void**)&hh,  g_hh);
    cudaGetSymbolAddress((void**)&hl,  g_hl);
    cudaGetSymbolAddress((void**)&wih, g_wih);
    cudaGetSymbolAddress((void**)&wil, g_wil);
    cudaGetSymbolAddress((void**)&woh, g_woh);
    cudaGetSymbolAddress((void**)&wol, g_wol);
    cudaGetSymbolAddress((void**)&oh,  g_oh);
    cudaGetSymbolAddress((void**)&ol,  g_ol);
    cudaGetSymbolAddress((void**)&qh,  g_qh);
    cudaGetSymbolAddress((void**)&ql,  g_ql);
    cudaGetSymbolAddress((void**)&kh,  g_kh);
    cudaGetSymbolAddress((void**)&kl,  g_kl);
    cudaGetSymbolAddress((void**)&vh,  g_vh);
    cudaGetSymbolAddress((void**)&vl,  g_vl);

    cudaFuncSetAttribute(gemm_bf, cudaFuncAttributeMaxDynamicSharedMemorySize,
                         GEMM_SMEM);
    cudaFuncSetAttribute(flash_tc, cudaFuncAttributeMaxDynamicSharedMemorySize,
                         FLASH_SMEM);

    ln_kernel<<<TOKENS, 256>>>(x, hh, hl);
    split_kernel<<<(3 * DM * DM / 4 + 255) / 256, 256>>>(W_in, wih, wil,
                                                         3 * DM * DM / 4);
    split_kernel<<<(DM * DM / 4 + 255) / 256, 256>>>(W_o, woh, wol,
                                                     DM * DM / 4);

    dim3 g1(3 * DM / BN, TOKENS / BM);
    gemm_bf<<<g1, 256, GEMM_SMEM>>>(hh, hl, wih, wil, qkv, TOKENS, 3 * DM, DM);

    rope_split<<<TOKENS, 512>>>(qkv, qh, ql, kh, kl, vh, vl);

    dim3 g2(LSEQ / FQ, NH, NB);
    flash_tc<<<g2, 256, FLASH_SMEM>>>(qh, ql, kh, kl, vh, vl, oh, ol);

    dim3 g3(DM / BN, TOKENS / BM);
    gemm_bf<<<g3, 256, GEMM_SMEM>>>(oh, ol, woh, wol, out, TOKENS, DM, DM);
}

// round 14
// speedup vs baseline: 1.6263x; 1.6263x over previous
#include <cuda_runtime.h>
#include <cuda_bf16.h>
#include <cstdint>

#define TOKENS 8192
#define DM     1024
#define LSEQ   2048
#define NB     4
#define NH     16
#define DK     64

// Scratch (device globals — no allocation in kernel_launch)
__device__ float g_qkv[(size_t)TOKENS * 3 * DM]; // qkv fp32 (gemm out)
__device__ __nv_bfloat16 g_hh[TOKENS * DM];      // layernorm out hi
__device__ __nv_bfloat16 g_hl[TOKENS * DM];      // layernorm out lo
__device__ __nv_bfloat16 g_wih[3 * DM * DM];     // W_in hi
__device__ __nv_bfloat16 g_wil[3 * DM * DM];     // W_in lo
__device__ __nv_bfloat16 g_woh[DM * DM];         // W_o hi
__device__ __nv_bfloat16 g_wol[DM * DM];         // W_o lo
__device__ __nv_bfloat16 g_oh[TOKENS * DM];      // attention out hi
__device__ __nv_bfloat16 g_ol[TOKENS * DM];      // attention out lo
// pre-split roped q/k and v for flash
__device__ __nv_bfloat16 g_qh[TOKENS * DM], g_ql[TOKENS * DM];
__device__ __nv_bfloat16 g_kh[TOKENS * DM], g_kl[TOKENS * DM];
__device__ __nv_bfloat16 g_vh[TOKENS * DM], g_vl[TOKENS * DM];

// ===========================================================================
// Helpers
// ===========================================================================
__device__ __forceinline__ void mma_bf16(float* c, const uint32_t* a,
                                         const uint32_t* b) {
    asm volatile(
        "mma.sync.aligned.m16n8k16.row.col.f32.bf16.bf16.f32 "
        "{%0,%1,%2,%3}, {%4,%5,%6,%7}, {%8,%9}, {%0,%1,%2,%3};\n"
        : "+f"(c[0]), "+f"(c[1]), "+f"(c[2]), "+f"(c[3])
        : "r"(a[0]), "r"(a[1]), "r"(a[2]), "r"(a[3]), "r"(b[0]), "r"(b[1]));
}
__device__ __forceinline__ uint32_t pack2(__nv_bfloat16 lo, __nv_bfloat16 hi) {
    __nv_bfloat162 t = __halves2bfloat162(lo, hi);
    return *reinterpret_cast<uint32_t*>(&t);
}
__device__ __forceinline__ uint32_t smem_u32addr(const void* p) {
    uint32_t a;
    asm("{ .reg .u64 t; cvta.to.shared.u64 t, %1; cvt.u32.u64 %0, t; }"
        : "=r"(a) : "l"(p));
    return a;
}
__device__ __forceinline__ void ldmx4(uint32_t& r0, uint32_t& r1,
                                      uint32_t& r2, uint32_t& r3,
                                      uint32_t addr) {
    asm volatile(
        "ldmatrix.sync.aligned.m8n8.x4.shared.b16 {%0,%1,%2,%3}, [%4];"
        : "=r"(r0), "=r"(r1), "=r"(r2), "=r"(r3) : "r"(addr));
}
__device__ __forceinline__ void ldmx4t(uint32_t& r0, uint32_t& r1,
                                       uint32_t& r2, uint32_t& r3,
                                       uint32_t addr) {
    asm volatile(
        "ldmatrix.sync.aligned.m8n8.x4.trans.shared.b16 {%0,%1,%2,%3}, [%4];"
        : "=r"(r0), "=r"(r1), "=r"(r2), "=r"(r3) : "r"(addr));
}
__device__ __forceinline__ void cp16(uint32_t dst, const void* src) {
    asm volatile("cp.async.cg.shared.global [%0], [%1], 16;"
                 :: "r"(dst), "l"(src) : "memory");
}
#define CP_COMMIT() asm volatile("cp.async.commit_group;" ::: "memory")
#define CP_WAIT0()  asm volatile("cp.async.wait_group 0;" ::: "memory")
#define CP_WAIT1()  asm volatile("cp.async.wait_group 1;" ::: "memory")

__device__ __forceinline__ void split4(float4 v, uint32_t& h0, uint32_t& h1,
                                       uint32_t& l0, uint32_t& l1) {
    __nv_bfloat16 hx = __float2bfloat16_rn(v.x);
    __nv_bfloat16 hy = __float2bfloat16_rn(v.y);
    __nv_bfloat16 hz = __float2bfloat16_rn(v.z);
    __nv_bfloat16 hw = __float2bfloat16_rn(v.w);
    h0 = pack2(hx, hy); h1 = pack2(hz, hw);
    l0 = pack2(__float2bfloat16_rn(v.x - __bfloat162float(hx)),
               __float2bfloat16_rn(v.y - __bfloat162float(hy)));
    l1 = pack2(__float2bfloat16_rn(v.z - __bfloat162float(hz)),
               __float2bfloat16_rn(v.w - __bfloat162float(hw)));
}
// split 2 floats -> (hi u32, lo u32)
__device__ __forceinline__ void split2(float a, float b, uint32_t& h, uint32_t& l) {
    __nv_bfloat16 ha = __float2bfloat16_rn(a);
    __nv_bfloat16 hb = __float2bfloat16_rn(b);
    h = pack2(ha, hb);
    l = pack2(__float2bfloat16_rn(a - __bfloat162float(ha)),
              __float2bfloat16_rn(b - __bfloat162float(hb)));
}

// ===========================================================================
// LayerNorm: one block per row, writes bf16 hi/lo split directly
// ===========================================================================
__global__ __launch_bounds__(256) void ln_kernel(const float* __restrict__ x,
                                                 __nv_bfloat16* __restrict__ hh,
                                                 __nv_bfloat16* __restrict__ hl) {
    int row = blockIdx.x;
    int t = threadIdx.x;
    const float4* xr = (const float4*)(x + (size_t)row * DM);
    float4 v = xr[t];
    float s  = v.x + v.y + v.z + v.w;
    float ss = v.x * v.x + v.y * v.y + v.z * v.z + v.w * v.w;
    #pragma unroll
    for (int off = 16; off; off >>= 1) {
        s  += __shfl_xor_sync(0xffffffffu, s, off);
        ss += __shfl_xor_sync(0xffffffffu, ss, off);
    }
    __shared__ float sh[16];
    __shared__ float sh_mu, sh_r;
    int warp = t >> 5, lane = t & 31;
    if (lane == 0) { sh[warp] = s; sh[warp + 8] = ss; }
    __syncthreads();
    if (t == 0) {
        float S = 0.f, SS = 0.f;
        #pragma unroll
        for (int w = 0; w < 8; w++) { S += sh[w]; SS += sh[w + 8]; }
        float mu  = S * (1.0f / DM);
        float var = SS * (1.0f / DM) - mu * mu;
        sh_mu = mu;
        sh_r  = rsqrtf(var + 1e-8f);
    }
    __syncthreads();
    float mu = sh_mu, r = sh_r;
    float4 o = make_float4((v.x - mu) * r, (v.y - mu) * r,
                           (v.z - mu) * r, (v.w - mu) * r);
    uint32_t h0, h1, l0, l1;
    split4(o, h0, h1, l0, l1);
    uint32_t* hw = (uint32_t*)(hh + (size_t)row * DM);
    uint32_t* lw = (uint32_t*)(hl + (size_t)row * DM);
    hw[2 * t] = h0; hw[2 * t + 1] = h1;
    lw[2 * t] = l0; lw[2 * t + 1] = l1;
}

// ===========================================================================
// Weight split: fp32 -> bf16 hi/lo
// ===========================================================================
__global__ __launch_bounds__(256) void split_kernel(const float* __restrict__ src,
                                                    __nv_bfloat16* __restrict__ hi,
                                                    __nv_bfloat16* __restrict__ lo,
                                                    int n4) {
    int i = blockIdx.x * blockDim.x + threadIdx.x;
    if (i >= n4) return;
    float4 v = ((const float4*)src)[i];
    uint32_t h0, h1, l0, l1;
    split4(v, h0, h1, l0, l1);
    ((uint32_t*)hi)[2 * i] = h0; ((uint32_t*)hi)[2 * i + 1] = h1;
    ((uint32_t*)lo)[2 * i] = l0; ((uint32_t*)lo)[2 * i + 1] = l1;
}

// ===========================================================================
// RoPE + split: read qkv fp32, apply rope to q,k, split q/k/v to bf16 hi/lo.
// ===========================================================================
__global__ __launch_bounds__(512) void rope_split(const float* __restrict__ qkv,
        __nv_bfloat16* __restrict__ qh, __nv_bfloat16* __restrict__ ql,
        __nv_bfloat16* __restrict__ kh, __nv_bfloat16* __restrict__ kl,
        __nv_bfloat16* __restrict__ vh, __nv_bfloat16* __restrict__ vl) {
    int token = blockIdx.x;
    int p = threadIdx.x;
    int head = p >> 5;
    int i = p & 31;
    int l = token & (LSEQ - 1);
    double inv = pow(10000.0, -(double)i / 32.0);
    double ang = (double)l * inv;
    double snd, csd;
    sincos(ang, &snd, &csd);
    float sn = (float)snd, cs = (float)csd;
    size_t base = (size_t)token * 3 * DM + head * DK + 2 * i;
    size_t di = ((size_t)token * DM + head * DK + 2 * i) >> 1;  // u32 index
    uint32_t h, lo;
    float x1 = qkv[base], x2 = qkv[base + 1];
    split2(x1 * cs - x2 * sn, x1 * sn + x2 * cs, h, lo);
    ((uint32_t*)qh)[di] = h; ((uint32_t*)ql)[di] = lo;
    float y1 = qkv[base + DM], y2 = qkv[base + DM + 1];
    split2(y1 * cs - y2 * sn, y1 * sn + y2 * cs, h, lo);
    ((uint32_t*)kh)[di] = h; ((uint32_t*)kl)[di] = lo;
    split2(qkv[base + 2 * DM], qkv[base + 2 * DM + 1], h, lo);
    ((uint32_t*)vh)[di] = h; ((uint32_t*)vl)[di] = lo;
}

// ===========================================================================
// Split-bf16 NT GEMM — EXACT R12 configuration (2-stage, wait_group 0,
// 2 CTAs/SM). Best measured: 469 us QKV, tensor=54.3%.
// ===========================================================================
#define BM 128
#define BN 128
#define SROW 12
#define SARR (BM * SROW)              // 1536 u32
#define SSTAGE (4 * SARR)
#define GEMM_SMEM (2 * SSTAGE * 4)    // 49152 B

__global__ __launch_bounds__(256, 2) void gemm_bf(
    const __nv_bfloat16* __restrict__ Ah, const __nv_bfloat16* __restrict__ Al,
    const __nv_bfloat16* __restrict__ Bh, const __nv_bfloat16* __restrict__ Bl,
    float* __restrict__ C, int M, int N_, int K) {
    extern __shared__ uint32_t smu[];
    int t = threadIdx.x;
    int lane = t & 31, wid = t >> 5;
    int wm = wid >> 2, wn = wid & 3;
    int g = lane >> 2, t4 = lane & 3;
    int m0 = blockIdx.y * BM, n0 = blockIdx.x * BN;

    float acc[4][4][4];
    #pragma unroll
    for (int i = 0; i < 4; i++)
        #pragma unroll
        for (int j = 0; j < 4; j++)
            #pragma unroll
            for (int q = 0; q < 4; q++) acc[i][j][q] = 0.f;

    int lrow = t >> 1, lhalf = t & 1;
    uint32_t sbase = smem_u32addr(smu);
    uint32_t sdst = sbase + (lrow * SROW + lhalf * 4) * 4;
    const __nv_bfloat16* ap  = Ah + (size_t)(m0 + lrow) * K + lhalf * 8;
    const __nv_bfloat16* alp = Al + (size_t)(m0 + lrow) * K + lhalf * 8;
    const __nv_bfloat16* bp  = Bh + (size_t)(n0 + lrow) * K + lhalf * 8;
    const __nv_bfloat16* blp = Bl + (size_t)(n0 + lrow) * K + lhalf * 8;

    const int NST = K / 16;
    cp16(sdst,                ap);
    cp16(sdst + SARR * 4,     alp);
    cp16(sdst + 2 * SARR * 4, bp);
    cp16(sdst + 3 * SARR * 4, blp);
    CP_COMMIT();

    int r8 = lane & 7, mat = lane >> 3;
    int a_loff = ((wm * 64 + (mat & 1) * 8 + r8) * SROW + (mat >> 1) * 4) * 4;
    int b_loff = ((wn * 32 + (mat >> 1) * 8 + r8) * SROW + (mat & 1) * 4) * 4;

    for (int s = 0; s < NST; s++) {
        CP_WAIT0();
        __syncthreads();
        if (s + 1 < NST) {
            int k0 = (s + 1) * 16;
            uint32_t db = sbase + ((s + 1) & 1) * (SSTAGE * 4) +
                          (lrow * SROW + lhalf * 4) * 4;
            cp16(db,                ap + k0);
            cp16(db + SARR * 4,     alp + k0);
            cp16(db + 2 * SARR * 4, bp + k0);
            cp16(db + 3 * SARR * 4, blp + k0);
            CP_COMMIT();
        }

        uint32_t stb = sbase + (s & 1) * (SSTAGE * 4);
        uint32_t bh[4][2], bl[4][2];
        #pragma unroll
        for (int p = 0; p < 2; p++) {
            ldmx4(bh[2 * p][0], bh[2 * p][1], bh[2 * p + 1][0], bh[2 * p + 1][1],
                  stb + 2 * SARR * 4 + b_loff + p * (16 * SROW * 4));
            ldmx4(bl[2 * p][0], bl[2 * p][1], bl[2 * p + 1][0], bl[2 * p + 1][1],
                  stb + 3 * SARR * 4 + b_loff + p * (16 * SROW * 4));
        }
        #pragma unroll
        for (int mb = 0; mb < 4; mb++) {
            uint32_t ah[4], al[4];
            ldmx4(ah[0], ah[1], ah[2], ah[3],
                  stb + a_loff + mb * (16 * SROW * 4));
            ldmx4(al[0], al[1], al[2], al[3],
                  stb + SARR * 4 + a_loff + mb * (16 * SROW * 4));
            #pragma unroll
            for (int nb = 0; nb < 4; nb++) {
                mma_bf16(acc[mb][nb], ah, bh[nb]);
                mma_bf16(acc[mb][nb], ah, bl[nb]);
                mma_bf16(acc[mb][nb], al, bh[nb]);
            }
        }
    }

    #pragma unroll
    for (int mb = 0; mb < 4; mb++) {
        int row = m0 + wm * 64 + mb * 16 + g;
        #pragma unroll
        for (int nb = 0; nb < 4; nb++) {
            int col = n0 + wn * 32 + nb * 8 + 2 * t4;
            *(float2*)(C + (size_t)row * N_ + col) =
                make_float2(acc[mb][nb][0], acc[mb][nb][1]);
            *(float2*)(C + (size_t)(row + 8) * N_ + col) =
                make_float2(acc[mb][nb][2], acc[mb][nb][3]);
        }
    }
}

// ===========================================================================
// Tensor-core causal flash attention. Pre-split bf16 inputs, cp.async
// staging, double-buffered K/V tiles. Epilogue writes bf16 hi/lo.
// ===========================================================================
#define FQ 128
#define FK 64
#define FR 36                          // u32 row stride (144 B)
#define OQH 0
#define OQL (FQ * FR)                  // 4608
#define KV0 (2 * FQ * FR)              // 9216
#define SST (4 * FK * FR)              // 9216 u32 per stage
#define KH_O 0
#define KL_O (FK * FR)                 // 2304
#define VH_O (2 * FK * FR)
#define VL_O (3 * FK * FR)
#define FLASH_SMEM ((KV0 + 2 * SST) * 4)   // 110592 B

__global__ __launch_bounds__(256) void flash_tc(
        const __nv_bfloat16* __restrict__ qhp, const __nv_bfloat16* __restrict__ qlp,
        const __nv_bfloat16* __restrict__ khp, const __nv_bfloat16* __restrict__ klp,
        const __nv_bfloat16* __restrict__ vhp, const __nv_bfloat16* __restrict__ vlp,
        __nv_bfloat16* __restrict__ oh, __nv_bfloat16* __restrict__ ol) {
    extern __shared__ uint32_t su[];
    int t = threadIdx.x;
    int lane = t & 31, wq = t >> 5;
    int g = lane >> 2, t4 = lane & 3;
    int qt = (int)gridDim.x - 1 - (int)blockIdx.x;
    int h = blockIdx.y, b = blockIdx.z;
    int qbase = qt * FQ;
    uint32_t sbase = smem_u32addr(su);

    // ---- Q staging via cp.async (group 0) ----
    {
        size_t qoff = (size_t)(b * LSEQ + qbase) * DM + h * DK;
        #pragma unroll
        for (int it = 0; it < 4; it++) {
            int f = t + it * 256;           // 0..1023
            int row = f >> 3, c = f & 7;
            uint32_t d = sbase + row * 144 + c * 16;
            cp16(d,           qhp + qoff + (size_t)row * DM + c * 8);
            cp16(d + OQL * 4, qlp + qoff + (size_t)row * DM + c * 8);
        }
        CP_COMMIT();
    }
    // ---- K/V tile 0 staging (group 1) ----
    int nkt = 2 * qt + 2;
    {
        size_t koff = (size_t)(b * LSEQ) * DM + h * DK;
        #pragma unroll
        for (int it = 0; it < 2; it++) {
            int f = t + it * 256;           // 0..511
            int row = f >> 3, c = f & 7;
            uint32_t d = sbase + KV0 * 4 + row * 144 + c * 16;
            size_t s = koff + (size_t)row * DM + c * 8;
            cp16(d,            khp + s);
            cp16(d + KL_O * 4, klp + s);
            cp16(d + VH_O * 4, vhp + s);
            cp16(d + VL_O * 4, vlp + s);
        }
        CP_COMMIT();
    }
    CP_WAIT1();                 // Q done
    __syncthreads();

    uint32_t qah[4][4], qal[4][4];
    #pragma unroll
    for (int s = 0; s < 4; s++) {
        int idx = (wq * 16 + g) * FR + 8 * s + t4;
        qah[s][0] = su[OQH + idx];          qah[s][1] = su[OQH + idx + 8 * FR];
        qah[s][2] = su[OQH + idx + 4];      qah[s][3] = su[OQH + idx + 8 * FR + 4];
        qal[s][0] = su[OQL + idx];          qal[s][1] = su[OQL + idx + 8 * FR];
        qal[s][2] = su[OQL + idx + 4];      qal[s][3] = su[OQL + idx + 8 * FR + 4];
    }

    float of[8][4];
    #pragma unroll
    for (int n = 0; n < 8; n++)
        #pragma unroll
        for (int c = 0; c < 4; c++) of[n][c] = 0.f;
    float m0 = -1e30f, m1 = -1e30f, l0 = 0.f, l1 = 0.f;

    int voff = ((lane & 15) * FR + (lane >> 4) * 4) * 4;
    int row0 = qbase + wq * 16 + g;

    for (int kt = 0; kt < nkt; kt++) {
        CP_WAIT0();             // tile kt staged
        __syncthreads();
        int st = kt & 1;
        if (kt + 1 < nkt) {
            size_t koff = (size_t)(b * LSEQ + (kt + 1) * FK) * DM + h * DK;
            uint32_t dbase = sbase + (KV0 + (1 - st) * SST) * 4;
            #pragma unroll
            for (int it = 0; it < 2; it++) {
                int f = t + it * 256;
                int row = f >> 3, c = f & 7;
                uint32_t d = dbase + row * 144 + c * 16;
                size_t s = koff + (size_t)row * DM + c * 8;
                cp16(d,            khp + s);
                cp16(d + KL_O * 4, klp + s);
                cp16(d + VH_O * 4, vhp + s);
                cp16(d + VL_O * 4, vlp + s);
            }
        }
        CP_COMMIT();

        int ktb = kt * FK;
        bool active = (ktb <= qbase + wq * 16);
        if (active) {
            const uint32_t* stK = su + KV0 + st * SST;
            uint32_t vb_h = sbase + (KV0 + st * SST + VH_O) * 4;
            uint32_t vb_l = sbase + (KV0 + st * SST + VL_O) * 4;

            float sf[8][4];
            #pragma unroll
            for (int j = 0; j < 8; j++)
                #pragma unroll
                for (int c = 0; c < 4; c++) sf[j][c] = 0.f;
            #pragma unroll
            for (int s = 0; s < 4; s++) {
                #pragma unroll
                for (int j = 0; j < 8; j++) {
                    int idx = (8 * j + g) * FR + 8 * s + t4;
                    uint32_t kb2[2], kl2[2];
                    kb2[0] = stK[KH_O + idx]; kb2[1] = stK[KH_O + idx + 4];
                    kl2[0] = stK[KL_O + idx]; kl2[1] = stK[KL_O + idx + 4];
                    mma_bf16(sf[j], qah[s], kb2);
                    mma_bf16(sf[j], qal[s], kb2);
                    mma_bf16(sf[j], qah[s], kl2);
                }
            }

            const float scale = 0.125f;
            bool need_mask = (ktb + FK - 1 > qbase + wq * 16);
            #pragma unroll
            for (int j = 0; j < 8; j++) {
                int col = ktb + 8 * j + 2 * t4;
                #pragma unroll
                for (int c = 0; c < 4; c++) {
                    float v = sf[j][c] * scale;
                    if (need_mask) {
                        int cc = col + (c & 1);
                        int rr = row0 + (c >> 1) * 8;
                        if (cc > rr) v = -1e30f;
                    }
                    sf[j][c] = v;
                }
            }

            float mx0 = -1e30f, mx1 = -1e30f;
            #pragma unroll
            for (int j = 0; j < 8; j++) {
                mx0 = fmaxf(mx0, fmaxf(sf[j][0], sf[j][1]));
                mx1 = fmaxf(mx1, fmaxf(sf[j][2], sf[j][3]));
            }
            mx0 = fmaxf(mx0, __shfl_xor_sync(0xffffffffu, mx0, 1));
            mx0 = fmaxf(mx0, __shfl_xor_sync(0xffffffffu, mx0, 2));
            mx1 = fmaxf(mx1, __shfl_xor_sync(0xffffffffu, mx1, 1));
            mx1 = fmaxf(mx1, __shfl_xor_sync(0xffffffffu, mx1, 2));
            float mn0 = fmaxf(m0, mx0), mn1 = fmaxf(m1, mx1);
            float a0 = __expf(m0 - mn0), a1 = __expf(m1 - mn1);
            m0 = mn0; m1 = mn1;
            float s0 = 0.f, s1 = 0.f;
            #pragma unroll
            for (int j = 0; j < 8; j++) {
                sf[j][0] = __expf(sf[j][0] - m0);
                sf[j][1] = __expf(sf[j][1] - m0);
                sf[j][2] = __expf(sf[j][2] - m1);
                sf[j][3] = __expf(sf[j][3] - m1);
                s0 += sf[j][0] + sf[j][1];
                s1 += sf[j][2] + sf[j][3];
            }
            s0 += __shfl_xor_sync(0xffffffffu, s0, 1);
            s0 += __shfl_xor_sync(0xffffffffu, s0, 2);
            s1 += __shfl_xor_sync(0xffffffffu, s1, 1);
            s1 += __shfl_xor_sync(0xffffffffu, s1, 2);
            l0 = l0 * a0 + s0;
            l1 = l1 * a1 + s1;
            #pragma unroll
            for (int n = 0; n < 8; n++) {
                of[n][0] *= a0; of[n][1] *= a0;
                of[n][2] *= a1; of[n][3] *= a1;
            }

            #pragma unroll
            for (int s = 0; s < 4; s++) {
                uint32_t pah[4], pal[4];
                #pragma unroll
                for (int half = 0; half < 2; half++) {
                    float p0 = sf[2 * s + half][0], p1 = sf[2 * s + half][1];
                    float p2 = sf[2 * s + half][2], p3 = sf[2 * s + half][3];
                    split2(p0, p1, pah[2 * half], pal[2 * half]);
                    split2(p2, p3, pah[2 * half + 1], pal[2 * half + 1]);
                }
                #pragma unroll
                for (int j2 = 0; j2 < 4; j2++) {
                    uint32_t vh0, vh1, vh2, vh3, vl0, vl1, vl2, vl3;
                    uint32_t boff2 = (16 * s * FR + 8 * j2) * 4 + voff;
                    ldmx4t(vh0, vh1, vh2, vh3, vb_h + boff2);
                    ldmx4t(vl0, vl1, vl2, vl3, vb_l + boff2);
                    uint32_t bh0[2] = {vh0, vh1}, bh1[2] = {vh2, vh3};
                    uint32_t bl0[2] = {vl0, vl1}, bl1[2] = {vl2, vl3};
                    mma_bf16(of[2 * j2], pah, bh0);
                    mma_bf16(of[2 * j2], pal, bh0);
                    mma_bf16(of[2 * j2], pah, bl0);
                    mma_bf16(of[2 * j2 + 1], pah, bh1);
                    mma_bf16(of[2 * j2 + 1], pal, bh1);
                    mma_bf16(of[2 * j2 + 1], pah, bl1);
                }
            }
        }
        __syncthreads();
    }

    // ---- epilogue: write bf16 hi/lo split ----
    float i0 = 1.f / l0, i1 = 1.f / l1;
    size_t base0 = (size_t)(b * LSEQ + row0) * DM + h * DK;
    size_t base1 = base0 + 8 * DM;
    uint32_t* ohw = (uint32_t*)oh;
    uint32_t* olw = (uint32_t*)ol;
    #pragma unroll
    for (int n = 0; n < 8; n++) {
        int col = 8 * n + 2 * t4;
        uint32_t h0, l0w, h1, l1w;
        split2(of[n][0] * i0, of[n][1] * i0, h0, l0w);
        split2(of[n][2] * i1, of[n][3] * i1, h1, l1w);
        ohw[(base0 + col) >> 1] = h0;
        olw[(base0 + col) >> 1] = l0w;
        ohw[(base1 + col) >> 1] = h1;
        olw[(base1 + col) >> 1] = l1w;
    }
}

// ===========================================================================
extern "C" void kernel_launch(void* const* d_in, const int* in_sizes, int n_in,
                              void* d_out, int out_size) {
    const float* x    = (const float*)d_in[0];
    const float* W_in = (const float*)d_in[1];
    const float* W_o  = (const float*)d_in[2];
    float* out = (float*)d_out;

    float* qkv;
    __nv_bfloat16 *hh, *hl, *wih, *wil, *woh, *wol, *oh, *ol;
    __nv_bfloat16 *qh, *ql, *kh, *kl, *vh, *vl;
    cudaGetSymbolAddress((void**)&qkv, g_qkv);
    cudaGetSymbolAddress((void**)&hh,  g_hh);
    cudaGetSymbolAddress((void**)&hl,  g_hl);
    cudaGetSymbolAddress((void**)&wih, g_wih);
    cudaGetSymbolAddress((void**)&wil, g_wil);
    cudaGetSymbolAddress((void**)&woh, g_woh);
    cudaGetSymbolAddress((void**)&wol, g_wol);
    cudaGetSymbolAddress((void**)&oh,  g_oh);
    cudaGetSymbolAddress((void**)&ol,  g_ol);
    cudaGetSymbolAddress((void**)&qh,  g_qh);
    cudaGetSymbolAddress((void**)&ql,  g_ql);
    cudaGetSymbolAddress((void**)&kh,  g_kh);
    cudaGetSymbolAddress((void**)&kl,  g_kl);
    cudaGetSymbolAddress((void**)&vh,  g_vh);
    cudaGetSymbolAddress((void**)&vl,  g_vl);

    cudaFuncSetAttribute(gemm_bf, cudaFuncAttributeMaxDynamicSharedMemorySize,
                         GEMM_SMEM);
    cudaFuncSetAttribute(flash_tc, cudaFuncAttributeMaxDynamicSharedMemorySize,
                         FLASH_SMEM);

    ln_kernel<<<TOKENS, 256>>>(x, hh, hl);
    split_kernel<<<(3 * DM * DM / 4 + 255) / 256, 256>>>(W_in, wih, wil,
                                                         3 * DM * DM / 4);
    split_kernel<<<(DM * DM / 4 + 255) / 256, 256>>>(W_o, woh, wol,
                                                     DM * DM / 4);

    dim3 g1(3 * DM / BN, TOKENS / BM);
    gemm_bf<<<g1, 256, GEMM_SMEM>>>(hh, hl, wih, wil, qkv, TOKENS, 3 * DM, DM);

    rope_split<<<TOKENS, 512>>>(qkv, qh, ql, kh, kl, vh, vl);

    dim3 g2(LSEQ / FQ, NH, NB);
    flash_tc<<<g2, 256, FLASH_SMEM>>>(qh, ql, kh, kl, vh, vl, oh, ol);

    dim3 g3(DM / BN, TOKENS / BM);
    gemm_bf<<<g3, 256, GEMM_SMEM>>>(oh, ol, woh, wol, out, TOKENS, DM, DM);
}

// round 15
// speedup vs baseline: 1.6896x; 1.0389x over previous
#include <cuda_runtime.h>
#include <cuda_bf16.h>
#include <cstdint>

#define TOKENS 8192
#define DM     1024
#define LSEQ   2048
#define NB     4
#define NH     16
#define DK     64

// Scratch (device globals — no allocation in kernel_launch)
__device__ float g_qkv[(size_t)TOKENS * 3 * DM]; // qkv fp32 (gemm out)
__device__ __nv_bfloat16 g_hh[TOKENS * DM];      // layernorm out hi
__device__ __nv_bfloat16 g_hl[TOKENS * DM];      // layernorm out lo
__device__ __nv_bfloat16 g_wih[3 * DM * DM];     // W_in hi
__device__ __nv_bfloat16 g_wil[3 * DM * DM];     // W_in lo
__device__ __nv_bfloat16 g_woh[DM * DM];         // W_o hi
__device__ __nv_bfloat16 g_wol[DM * DM];         // W_o lo
__device__ __nv_bfloat16 g_oh[TOKENS * DM];      // attention out hi
__device__ __nv_bfloat16 g_ol[TOKENS * DM];      // attention out lo
// pre-split roped q/k and v for flash
__device__ __nv_bfloat16 g_qh[TOKENS * DM], g_ql[TOKENS * DM];
__device__ __nv_bfloat16 g_kh[TOKENS * DM], g_kl[TOKENS * DM];
__device__ __nv_bfloat16 g_vh[TOKENS * DM], g_vl[TOKENS * DM];

// ===========================================================================
// Helpers
// ===========================================================================
__device__ __forceinline__ void mma_bf16(float* c, const uint32_t* a,
                                         const uint32_t* b) {
    asm volatile(
        "mma.sync.aligned.m16n8k16.row.col.f32.bf16.bf16.f32 "
        "{%0,%1,%2,%3}, {%4,%5,%6,%7}, {%8,%9}, {%0,%1,%2,%3};\n"
        : "+f"(c[0]), "+f"(c[1]), "+f"(c[2]), "+f"(c[3])
        : "r"(a[0]), "r"(a[1]), "r"(a[2]), "r"(a[3]), "r"(b[0]), "r"(b[1]));
}
__device__ __forceinline__ uint32_t pack2(__nv_bfloat16 lo, __nv_bfloat16 hi) {
    __nv_bfloat162 t = __halves2bfloat162(lo, hi);
    return *reinterpret_cast<uint32_t*>(&t);
}
__device__ __forceinline__ uint32_t smem_u32addr(const void* p) {
    uint32_t a;
    asm("{ .reg .u64 t; cvta.to.shared.u64 t, %1; cvt.u32.u64 %0, t; }"
        : "=r"(a) : "l"(p));
    return a;
}
__device__ __forceinline__ void ldmx4(uint32_t& r0, uint32_t& r1,
                                      uint32_t& r2, uint32_t& r3,
                                      uint32_t addr) {
    asm volatile(
        "ldmatrix.sync.aligned.m8n8.x4.shared.b16 {%0,%1,%2,%3}, [%4];"
        : "=r"(r0), "=r"(r1), "=r"(r2), "=r"(r3) : "r"(addr));
}
__device__ __forceinline__ void ldmx4t(uint32_t& r0, uint32_t& r1,
                                       uint32_t& r2, uint32_t& r3,
                                       uint32_t addr) {
    asm volatile(
        "ldmatrix.sync.aligned.m8n8.x4.trans.shared.b16 {%0,%1,%2,%3}, [%4];"
        : "=r"(r0), "=r"(r1), "=r"(r2), "=r"(r3) : "r"(addr));
}
__device__ __forceinline__ void cp16(uint32_t dst, const void* src) {
    asm volatile("cp.async.cg.shared.global [%0], [%1], 16;"
                 :: "r"(dst), "l"(src) : "memory");
}
#define CP_COMMIT() asm volatile("cp.async.commit_group;" ::: "memory")
#define CP_WAIT0()  asm volatile("cp.async.wait_group 0;" ::: "memory")
#define CP_WAIT1()  asm volatile("cp.async.wait_group 1;" ::: "memory")

__device__ __forceinline__ void split4(float4 v, uint32_t& h0, uint32_t& h1,
                                       uint32_t& l0, uint32_t& l1) {
    __nv_bfloat16 hx = __float2bfloat16_rn(v.x);
    __nv_bfloat16 hy = __float2bfloat16_rn(v.y);
    __nv_bfloat16 hz = __float2bfloat16_rn(v.z);
    __nv_bfloat16 hw = __float2bfloat16_rn(v.w);
    h0 = pack2(hx, hy); h1 = pack2(hz, hw);
    l0 = pack2(__float2bfloat16_rn(v.x - __bfloat162float(hx)),
               __float2bfloat16_rn(v.y - __bfloat162float(hy)));
    l1 = pack2(__float2bfloat16_rn(v.z - __bfloat162float(hz)),
               __float2bfloat16_rn(v.w - __bfloat162float(hw)));
}
// split 2 floats -> (hi u32, lo u32)
__device__ __forceinline__ void split2(float a, float b, uint32_t& h, uint32_t& l) {
    __nv_bfloat16 ha = __float2bfloat16_rn(a);
    __nv_bfloat16 hb = __float2bfloat16_rn(b);
    h = pack2(ha, hb);
    l = pack2(__float2bfloat16_rn(a - __bfloat162float(ha)),
              __float2bfloat16_rn(b - __bfloat162float(hb)));
}

// ===========================================================================
// LayerNorm: one block per row, writes bf16 hi/lo split directly
// ===========================================================================
__global__ __launch_bounds__(256) void ln_kernel(const float* __restrict__ x,
                                                 __nv_bfloat16* __restrict__ hh,
                                                 __nv_bfloat16* __restrict__ hl) {
    int row = blockIdx.x;
    int t = threadIdx.x;
    const float4* xr = (const float4*)(x + (size_t)row * DM);
    float4 v = xr[t];
    float s  = v.x + v.y + v.z + v.w;
    float ss = v.x * v.x + v.y * v.y + v.z * v.z + v.w * v.w;
    #pragma unroll
    for (int off = 16; off; off >>= 1) {
        s  += __shfl_xor_sync(0xffffffffu, s, off);
        ss += __shfl_xor_sync(0xffffffffu, ss, off);
    }
    __shared__ float sh[16];
    __shared__ float sh_mu, sh_r;
    int warp = t >> 5, lane = t & 31;
    if (lane == 0) { sh[warp] = s; sh[warp + 8] = ss; }
    __syncthreads();
    if (t == 0) {
        float S = 0.f, SS = 0.f;
        #pragma unroll
        for (int w = 0; w < 8; w++) { S += sh[w]; SS += sh[w + 8]; }
        float mu  = S * (1.0f / DM);
        float var = SS * (1.0f / DM) - mu * mu;
        sh_mu = mu;
        sh_r  = rsqrtf(var + 1e-8f);
    }
    __syncthreads();
    float mu = sh_mu, r = sh_r;
    float4 o = make_float4((v.x - mu) * r, (v.y - mu) * r,
                           (v.z - mu) * r, (v.w - mu) * r);
    uint32_t h0, h1, l0, l1;
    split4(o, h0, h1, l0, l1);
    uint32_t* hw = (uint32_t*)(hh + (size_t)row * DM);
    uint32_t* lw = (uint32_t*)(hl + (size_t)row * DM);
    hw[2 * t] = h0; hw[2 * t + 1] = h1;
    lw[2 * t] = l0; lw[2 * t + 1] = l1;
}

// ===========================================================================
// Weight split: fp32 -> bf16 hi/lo
// ===========================================================================
__global__ __launch_bounds__(256) void split_kernel(const float* __restrict__ src,
                                                    __nv_bfloat16* __restrict__ hi,
                                                    __nv_bfloat16* __restrict__ lo,
                                                    int n4) {
    int i = blockIdx.x * blockDim.x + threadIdx.x;
    if (i >= n4) return;
    float4 v = ((const float4*)src)[i];
    uint32_t h0, h1, l0, l1;
    split4(v, h0, h1, l0, l1);
    ((uint32_t*)hi)[2 * i] = h0; ((uint32_t*)hi)[2 * i + 1] = h1;
    ((uint32_t*)lo)[2 * i] = l0; ((uint32_t*)lo)[2 * i + 1] = l1;
}

// ===========================================================================
// RoPE + split: read qkv fp32, apply rope to q,k, split q/k/v to bf16 hi/lo.
// ===========================================================================
__global__ __launch_bounds__(512) void rope_split(const float* __restrict__ qkv,
        __nv_bfloat16* __restrict__ qh, __nv_bfloat16* __restrict__ ql,
        __nv_bfloat16* __restrict__ kh, __nv_bfloat16* __restrict__ kl,
        __nv_bfloat16* __restrict__ vh, __nv_bfloat16* __restrict__ vl) {
    int token = blockIdx.x;
    int p = threadIdx.x;
    int head = p >> 5;
    int i = p & 31;
    int l = token & (LSEQ - 1);
    double inv = pow(10000.0, -(double)i / 32.0);
    double ang = (double)l * inv;
    double snd, csd;
    sincos(ang, &snd, &csd);
    float sn = (float)snd, cs = (float)csd;
    size_t base = (size_t)token * 3 * DM + head * DK + 2 * i;
    size_t di = ((size_t)token * DM + head * DK + 2 * i) >> 1;  // u32 index
    uint32_t h, lo;
    float x1 = qkv[base], x2 = qkv[base + 1];
    split2(x1 * cs - x2 * sn, x1 * sn + x2 * cs, h, lo);
    ((uint32_t*)qh)[di] = h; ((uint32_t*)ql)[di] = lo;
    float y1 = qkv[base + DM], y2 = qkv[base + DM + 1];
    split2(y1 * cs - y2 * sn, y1 * sn + y2 * cs, h, lo);
    ((uint32_t*)kh)[di] = h; ((uint32_t*)kl)[di] = lo;
    split2(qkv[base + 2 * DM], qkv[base + 2 * DM + 1], h, lo);
    ((uint32_t*)vh)[di] = h; ((uint32_t*)vl)[di] = lo;
}

// ===========================================================================
// Split-bf16 NT GEMM — 128 threads (4 warps, 2x2 grid, warp tile 64x64),
// 128x128 CTA tile, 2-stage cp.async, 2 CTAs/SM. 33% less LDSM traffic
// than the 8-warp layout.
// ===========================================================================
#define BM 128
#define BN 128
#define SROW 12
#define SARR (BM * SROW)              // 1536 u32
#define SSTAGE (4 * SARR)
#define GEMM_SMEM (2 * SSTAGE * 4)    // 49152 B

__global__ __launch_bounds__(128, 2) void gemm_bf(
    const __nv_bfloat16* __restrict__ Ah, const __nv_bfloat16* __restrict__ Al,
    const __nv_bfloat16* __restrict__ Bh, const __nv_bfloat16* __restrict__ Bl,
    float* __restrict__ C, int M, int N_, int K) {
    extern __shared__ uint32_t smu[];
    int t = threadIdx.x;
    int lane = t & 31, wid = t >> 5;
    int wm = wid >> 1, wn = wid & 1;      // 2 x 2 warp grid, 64x64 tiles
    int g = lane >> 2, t4 = lane & 3;
    int m0 = blockIdx.y * BM, n0 = blockIdx.x * BN;

    float acc[4][8][4];
    #pragma unroll
    for (int i = 0; i < 4; i++)
        #pragma unroll
        for (int j = 0; j < 8; j++)
            #pragma unroll
            for (int q = 0; q < 4; q++) acc[i][j][q] = 0.f;

    // staging: 128 threads; thread t -> rows (t>>1, t>>1 + 64), k-half t&1
    int lrow = t >> 1, lhalf = t & 1;
    uint32_t sbase = smem_u32addr(smu);
    uint32_t so0 = (lrow * SROW + lhalf * 4) * 4;
    uint32_t so1 = ((lrow + 64) * SROW + lhalf * 4) * 4;
    const __nv_bfloat16* ap  = Ah + (size_t)(m0 + lrow) * K + lhalf * 8;
    const __nv_bfloat16* alp = Al + (size_t)(m0 + lrow) * K + lhalf * 8;
    const __nv_bfloat16* bp  = Bh + (size_t)(n0 + lrow) * K + lhalf * 8;
    const __nv_bfloat16* blp = Bl + (size_t)(n0 + lrow) * K + lhalf * 8;
    const size_t r64 = (size_t)64 * K;

    const int NST = K / 16;
    // prologue stage 0
    cp16(sbase + so0,                ap);
    cp16(sbase + so1,                ap + r64);
    cp16(sbase + SARR * 4 + so0,     alp);
    cp16(sbase + SARR * 4 + so1,     alp + r64);
    cp16(sbase + 2 * SARR * 4 + so0, bp);
    cp16(sbase + 2 * SARR * 4 + so1, bp + r64);
    cp16(sbase + 3 * SARR * 4 + so0, blp);
    cp16(sbase + 3 * SARR * 4 + so1, blp + r64);
    CP_COMMIT();

    // ldmatrix lane byte offsets
    int r8 = lane & 7, mat = lane >> 3;
    int a_loff = ((wm * 64 + (mat & 1) * 8 + r8) * SROW + (mat >> 1) * 4) * 4;
    int b_loff = ((wn * 64 + (mat >> 1) * 8 + r8) * SROW + (mat & 1) * 4) * 4;

    for (int s = 0; s < NST; s++) {
        CP_WAIT0();
        __syncthreads();
        if (s + 1 < NST) {
            int k0 = (s + 1) * 16;
            uint32_t db = sbase + ((s + 1) & 1) * (SSTAGE * 4);
            cp16(db + so0,                ap + k0);
            cp16(db + so1,                ap + r64 + k0);
            cp16(db + SARR * 4 + so0,     alp + k0);
            cp16(db + SARR * 4 + so1,     alp + r64 + k0);
            cp16(db + 2 * SARR * 4 + so0, bp + k0);
            cp16(db + 2 * SARR * 4 + so1, bp + r64 + k0);
            cp16(db + 3 * SARR * 4 + so0, blp + k0);
            cp16(db + 3 * SARR * 4 + so1, blp + r64 + k0);
            CP_COMMIT();
        }

        uint32_t stb = sbase + (s & 1) * (SSTAGE * 4);
        // B fragments resident for the stage: 8 nb (2 per ldmx4)
        uint32_t bh[8][2], bl[8][2];
        #pragma unroll
        for (int p = 0; p < 4; p++) {
            ldmx4(bh[2 * p][0], bh[2 * p][1], bh[2 * p + 1][0], bh[2 * p + 1][1],
                  stb + 2 * SARR * 4 + b_loff + p * (16 * SROW * 4));
            ldmx4(bl[2 * p][0], bl[2 * p][1], bl[2 * p + 1][0], bl[2 * p + 1][1],
                  stb + 3 * SARR * 4 + b_loff + p * (16 * SROW * 4));
        }
        // A fragments per mb
        #pragma unroll
        for (int mb = 0; mb < 4; mb++) {
            uint32_t ah[4], al[4];
            ldmx4(ah[0], ah[1], ah[2], ah[3],
                  stb + a_loff + mb * (16 * SROW * 4));
            ldmx4(al[0], al[1], al[2], al[3],
                  stb + SARR * 4 + a_loff + mb * (16 * SROW * 4));
            #pragma unroll
            for (int nb = 0; nb < 8; nb++) {
                mma_bf16(acc[mb][nb], ah, bh[nb]);
                mma_bf16(acc[mb][nb], ah, bl[nb]);
                mma_bf16(acc[mb][nb], al, bh[nb]);
            }
        }
    }

    #pragma unroll
    for (int mb = 0; mb < 4; mb++) {
        int row = m0 + wm * 64 + mb * 16 + g;
        #pragma unroll
        for (int nb = 0; nb < 8; nb++) {
            int col = n0 + wn * 64 + nb * 8 + 2 * t4;
            *(float2*)(C + (size_t)row * N_ + col) =
                make_float2(acc[mb][nb][0], acc[mb][nb][1]);
            *(float2*)(C + (size_t)(row + 8) * N_ + col) =
                make_float2(acc[mb][nb][2], acc[mb][nb][3]);
        }
    }
}

// ===========================================================================
// Tensor-core causal flash attention. Pre-split bf16 inputs, cp.async
// staging, double-buffered K/V tiles. Epilogue writes bf16 hi/lo.
// ===========================================================================
#define FQ 128
#define FK 64
#define FR 36                          // u32 row stride (144 B)
#define OQH 0
#define OQL (FQ * FR)                  // 4608
#define KV0 (2 * FQ * FR)              // 9216
#define SST (4 * FK * FR)              // 9216 u32 per stage
#define KH_O 0
#define KL_O (FK * FR)                 // 2304
#define VH_O (2 * FK * FR)
#define VL_O (3 * FK * FR)
#define FLASH_SMEM ((KV0 + 2 * SST) * 4)   // 110592 B

__global__ __launch_bounds__(256) void flash_tc(
        const __nv_bfloat16* __restrict__ qhp, const __nv_bfloat16* __restrict__ qlp,
        const __nv_bfloat16* __restrict__ khp, const __nv_bfloat16* __restrict__ klp,
        const __nv_bfloat16* __restrict__ vhp, const __nv_bfloat16* __restrict__ vlp,
        __nv_bfloat16* __restrict__ oh, __nv_bfloat16* __restrict__ ol) {
    extern __shared__ uint32_t su[];
    int t = threadIdx.x;
    int lane = t & 31, wq = t >> 5;
    int g = lane >> 2, t4 = lane & 3;
    int qt = (int)gridDim.x - 1 - (int)blockIdx.x;
    int h = blockIdx.y, b = blockIdx.z;
    int qbase = qt * FQ;
    uint32_t sbase = smem_u32addr(su);

    // ---- Q staging via cp.async (group 0) ----
    {
        size_t qoff = (size_t)(b * LSEQ + qbase) * DM + h * DK;
        #pragma unroll
        for (int it = 0; it < 4; it++) {
            int f = t + it * 256;           // 0..1023
            int row = f >> 3, c = f & 7;
            uint32_t d = sbase + row * 144 + c * 16;
            cp16(d,           qhp + qoff + (size_t)row * DM + c * 8);
            cp16(d + OQL * 4, qlp + qoff + (size_t)row * DM + c * 8);
        }
        CP_COMMIT();
    }
    // ---- K/V tile 0 staging (group 1) ----
    int nkt = 2 * qt + 2;
    {
        size_t koff = (size_t)(b * LSEQ) * DM + h * DK;
        #pragma unroll
        for (int it = 0; it < 2; it++) {
            int f = t + it * 256;           // 0..511
            int row = f >> 3, c = f & 7;
            uint32_t d = sbase + KV0 * 4 + row * 144 + c * 16;
            size_t s = koff + (size_t)row * DM + c * 8;
            cp16(d,            khp + s);
            cp16(d + KL_O * 4, klp + s);
            cp16(d + VH_O * 4, vhp + s);
            cp16(d + VL_O * 4, vlp + s);
        }
        CP_COMMIT();
    }
    CP_WAIT1();                 // Q done
    __syncthreads();

    uint32_t qah[4][4], qal[4][4];
    #pragma unroll
    for (int s = 0; s < 4; s++) {
        int idx = (wq * 16 + g) * FR + 8 * s + t4;
        qah[s][0] = su[OQH + idx];          qah[s][1] = su[OQH + idx + 8 * FR];
        qah[s][2] = su[OQH + idx + 4];      qah[s][3] = su[OQH + idx + 8 * FR + 4];
        qal[s][0] = su[OQL + idx];          qal[s][1] = su[OQL + idx + 8 * FR];
        qal[s][2] = su[OQL + idx + 4];      qal[s][3] = su[OQL + idx + 8 * FR + 4];
    }

    float of[8][4];
    #pragma unroll
    for (int n = 0; n < 8; n++)
        #pragma unroll
        for (int c = 0; c < 4; c++) of[n][c] = 0.f;
    float m0 = -1e30f, m1 = -1e30f, l0 = 0.f, l1 = 0.f;

    int voff = ((lane & 15) * FR + (lane >> 4) * 4) * 4;
    int row0 = qbase + wq * 16 + g;

    for (int kt = 0; kt < nkt; kt++) {
        CP_WAIT0();             // tile kt staged
        __syncthreads();
        int st = kt & 1;
        if (kt + 1 < nkt) {
            size_t koff = (size_t)(b * LSEQ + (kt + 1) * FK) * DM + h * DK;
            uint32_t dbase = sbase + (KV0 + (1 - st) * SST) * 4;
            #pragma unroll
            for (int it = 0; it < 2; it++) {
                int f = t + it * 256;
                int row = f >> 3, c = f & 7;
                uint32_t d = dbase + row * 144 + c * 16;
                size_t s = koff + (size_t)row * DM + c * 8;
                cp16(d,            khp + s);
                cp16(d + KL_O * 4, klp + s);
                cp16(d + VH_O * 4, vhp + s);
                cp16(d + VL_O * 4, vlp + s);
            }
        }
        CP_COMMIT();

        int ktb = kt * FK;
        bool active = (ktb <= qbase + wq * 16);
        if (active) {
            const uint32_t* stK = su + KV0 + st * SST;
            uint32_t vb_h = sbase + (KV0 + st * SST + VH_O) * 4;
            uint32_t vb_l = sbase + (KV0 + st * SST + VL_O) * 4;

            float sf[8][4];
            #pragma unroll
            for (int j = 0; j < 8; j++)
                #pragma unroll
                for (int c = 0; c < 4; c++) sf[j][c] = 0.f;
            #pragma unroll
            for (int s = 0; s < 4; s++) {
                #pragma unroll
                for (int j = 0; j < 8; j++) {
                    int idx = (8 * j + g) * FR + 8 * s + t4;
                    uint32_t kb2[2], kl2[2];
                    kb2[0] = stK[KH_O + idx]; kb2[1] = stK[KH_O + idx + 4];
                    kl2[0] = stK[KL_O + idx]; kl2[1] = stK[KL_O + idx + 4];
                    mma_bf16(sf[j], qah[s], kb2);
                    mma_bf16(sf[j], qal[s], kb2);
                    mma_bf16(sf[j], qah[s], kl2);
                }
            }

            const float scale = 0.125f;
            bool need_mask = (ktb + FK - 1 > qbase + wq * 16);
            #pragma unroll
            for (int j = 0; j < 8; j++) {
                int col = ktb + 8 * j + 2 * t4;
                #pragma unroll
                for (int c = 0; c < 4; c++) {
                    float v = sf[j][c] * scale;
                    if (need_mask) {
                        int cc = col + (c & 1);
                        int rr = row0 + (c >> 1) * 8;
                        if (cc > rr) v = -1e30f;
                    }
                    sf[j][c] = v;
                }
            }

            float mx0 = -1e30f, mx1 = -1e30f;
            #pragma unroll
            for (int j = 0; j < 8; j++) {
                mx0 = fmaxf(mx0, fmaxf(sf[j][0], sf[j][1]));
                mx1 = fmaxf(mx1, fmaxf(sf[j][2], sf[j][3]));
            }
            mx0 = fmaxf(mx0, __shfl_xor_sync(0xffffffffu, mx0, 1));
            mx0 = fmaxf(mx0, __shfl_xor_sync(0xffffffffu, mx0, 2));
            mx1 = fmaxf(mx1, __shfl_xor_sync(0xffffffffu, mx1, 1));
            mx1 = fmaxf(mx1, __shfl_xor_sync(0xffffffffu, mx1, 2));
            float mn0 = fmaxf(m0, mx0), mn1 = fmaxf(m1, mx1);
            float a0 = __expf(m0 - mn0), a1 = __expf(m1 - mn1);
            m0 = mn0; m1 = mn1;
            float s0 = 0.f, s1 = 0.f;
            #pragma unroll
            for (int j = 0; j < 8; j++) {
                sf[j][0] = __expf(sf[j][0] - m0);
                sf[j][1] = __expf(sf[j][1] - m0);
                sf[j][2] = __expf(sf[j][2] - m1);
                sf[j][3] = __expf(sf[j][3] - m1);
                s0 += sf[j][0] + sf[j][1];
                s1 += sf[j][2] + sf[j][3];
            }
            s0 += __shfl_xor_sync(0xffffffffu, s0, 1);
            s0 += __shfl_xor_sync(0xffffffffu, s0, 2);
            s1 += __shfl_xor_sync(0xffffffffu, s1, 1);
            s1 += __shfl_xor_sync(0xffffffffu, s1, 2);
            l0 = l0 * a0 + s0;
            l1 = l1 * a1 + s1;
            #pragma unroll
            for (int n = 0; n < 8; n++) {
                of[n][0] *= a0; of[n][1] *= a0;
                of[n][2] *= a1; of[n][3] *= a1;
            }

            #pragma unroll
            for (int s = 0; s < 4; s++) {
                uint32_t pah[4], pal[4];
                #pragma unroll
                for (int half = 0; half < 2; half++) {
                    float p0 = sf[2 * s + half][0], p1 = sf[2 * s + half][1];
                    float p2 = sf[2 * s + half][2], p3 = sf[2 * s + half][3];
                    split2(p0, p1, pah[2 * half], pal[2 * half]);
                    split2(p2, p3, pah[2 * half + 1], pal[2 * half + 1]);
                }
                #pragma unroll
                for (int j2 = 0; j2 < 4; j2++) {
                    uint32_t vh0, vh1, vh2, vh3, vl0, vl1, vl2, vl3;
                    uint32_t boff2 = (16 * s * FR + 8 * j2) * 4 + voff;
                    ldmx4t(vh0, vh1, vh2, vh3, vb_h + boff2);
                    ldmx4t(vl0, vl1, vl2, vl3, vb_l + boff2);
                    uint32_t bh0[2] = {vh0, vh1}, bh1[2] = {vh2, vh3};
                    uint32_t bl0[2] = {vl0, vl1}, bl1[2] = {vl2, vl3};
                    mma_bf16(of[2 * j2], pah, bh0);
                    mma_bf16(of[2 * j2], pal, bh0);
                    mma_bf16(of[2 * j2], pah, bl0);
                    mma_bf16(of[2 * j2 + 1], pah, bh1);
                    mma_bf16(of[2 * j2 + 1], pal, bh1);
                    mma_bf16(of[2 * j2 + 1], pah, bl1);
                }
            }
        }
        __syncthreads();
    }

    // ---- epilogue: write bf16 hi/lo split ----
    float i0 = 1.f / l0, i1 = 1.f / l1;
    size_t base0 = (size_t)(b * LSEQ + row0) * DM + h * DK;
    size_t base1 = base0 + 8 * DM;
    uint32_t* ohw = (uint32_t*)oh;
    uint32_t* olw = (uint32_t*)ol;
    #pragma unroll
    for (int n = 0; n < 8; n++) {
        int col = 8 * n + 2 * t4;
        uint32_t h0, l0w, h1, l1w;
        split2(of[n][0] * i0, of[n][1] * i0, h0, l0w);
        split2(of[n][2] * i1, of[n][3] * i1, h1, l1w);
        ohw[(base0 + col) >> 1] = h0;
        olw[(base0 + col) >> 1] = l0w;
        ohw[(base1 + col) >> 1] = h1;
        olw[(base1 + col) >> 1] = l1w;
    }
}

// ===========================================================================
extern "C" void kernel_launch(void* const* d_in, const int* in_sizes, int n_in,
                              void* d_out, int out_size) {
    const float* x    = (const float*)d_in[0];
    const float* W_in = (const float*)d_in[1];
    const float* W_o  = (const float*)d_in[2];
    float* out = (float*)d_out;

    float* qkv;
    __nv_bfloat16 *hh, *hl, *wih, *wil, *woh, *wol, *oh, *ol;
    __nv_bfloat16 *qh, *ql, *kh, *kl, *vh, *vl;
    cudaGetSymbolAddress((void**)&qkv, g_qkv);
    cudaGetSymbolAddress((void**)&hh,  g_hh);
    cudaGetSymbolAddress((void**)&hl,  g_hl);
    cudaGetSymbolAddress((void**)&wih, g_wih);
    cudaGetSymbolAddress((void**)&wil, g_wil);
    cudaGetSymbolAddress((void**)&woh, g_woh);
    cudaGetSymbolAddress((void**)&wol, g_wol);
    cudaGetSymbolAddress((void**)&oh,  g_oh);
    cudaGetSymbolAddress((void**)&ol,  g_ol);
    cudaGetSymbolAddress((void**)&qh,  g_qh);
    cudaGetSymbolAddress((void**)&ql,  g_ql);
    cudaGetSymbolAddress((void**)&kh,  g_kh);
    cudaGetSymbolAddress((void**)&kl,  g_kl);
    cudaGetSymbolAddress((void**)&vh,  g_vh);
    cudaGetSymbolAddress((void**)&vl,  g_vl);

    cudaFuncSetAttribute(gemm_bf, cudaFuncAttributeMaxDynamicSharedMemorySize,
                         GEMM_SMEM);
    cudaFuncSetAttribute(flash_tc, cudaFuncAttributeMaxDynamicSharedMemorySize,
                         FLASH_SMEM);

    ln_kernel<<<TOKENS, 256>>>(x, hh, hl);
    split_kernel<<<(3 * DM * DM / 4 + 255) / 256, 256>>>(W_in, wih, wil,
                                                         3 * DM * DM / 4);
    split_kernel<<<(DM * DM / 4 + 255) / 256, 256>>>(W_o, woh, wol,
                                                     DM * DM / 4);

    dim3 g1(3 * DM / BN, TOKENS / BM);
    gemm_bf<<<g1, 128, GEMM_SMEM>>>(hh, hl, wih, wil, qkv, TOKENS, 3 * DM, DM);

    rope_split<<<TOKENS, 512>>>(qkv, qh, ql, kh, kl, vh, vl);

    dim3 g2(LSEQ / FQ, NH, NB);
    flash_tc<<<g2, 256, FLASH_SMEM>>>(qh, ql, kh, kl, vh, vl, oh, ol);

    dim3 g3(DM / BN, TOKENS / BM);
    gemm_bf<<<g3, 128, GEMM_SMEM>>>(oh, ol, woh, wol, out, TOKENS, DM, DM);
}

// round 17
// speedup vs baseline: 3.0605x; 1.8114x over previous
#include <cuda_runtime.h>
#include <cuda_bf16.h>
#include <cstdint>

#define TOKENS 8192
#define DM     1024
#define LSEQ   2048
#define NB     4
#define NH     16
#define DK     64

// Scratch (device globals — no allocation in kernel_launch)
__device__ float g_qkv[(size_t)TOKENS * 3 * DM]; // qkv fp32 (gemm out)
__device__ __nv_bfloat16 g_hh[TOKENS * DM];      // layernorm out hi
__device__ __nv_bfloat16 g_hl[TOKENS * DM];      // layernorm out lo
__device__ __nv_bfloat16 g_wih[3 * DM * DM];     // W_in hi
__device__ __nv_bfloat16 g_wil[3 * DM * DM];     // W_in lo
__device__ __nv_bfloat16 g_woh[DM * DM];         // W_o hi
__device__ __nv_bfloat16 g_wol[DM * DM];         // W_o lo
__device__ __nv_bfloat16 g_oh[TOKENS * DM];      // attention out hi
__device__ __nv_bfloat16 g_ol[TOKENS * DM];      // attention out lo
// pre-split roped q/k and v for flash
__device__ __nv_bfloat16 g_qh[TOKENS * DM], g_ql[TOKENS * DM];
__device__ __nv_bfloat16 g_kh[TOKENS * DM], g_kl[TOKENS * DM];
__device__ __nv_bfloat16 g_vh[TOKENS * DM], g_vl[TOKENS * DM];
// rope trig table: (l, i) -> (cos, sin)
__device__ float2 g_trig[LSEQ * 32];

// ===========================================================================
// Helpers
// ===========================================================================
__device__ __forceinline__ void mma_bf16(float* c, const uint32_t* a,
                                         const uint32_t* b) {
    asm volatile(
        "mma.sync.aligned.m16n8k16.row.col.f32.bf16.bf16.f32 "
        "{%0,%1,%2,%3}, {%4,%5,%6,%7}, {%8,%9}, {%0,%1,%2,%3};\n"
        : "+f"(c[0]), "+f"(c[1]), "+f"(c[2]), "+f"(c[3])
        : "r"(a[0]), "r"(a[1]), "r"(a[2]), "r"(a[3]), "r"(b[0]), "r"(b[1]));
}
__device__ __forceinline__ uint32_t pack2(__nv_bfloat16 lo, __nv_bfloat16 hi) {
    __nv_bfloat162 t = __halves2bfloat162(lo, hi);
    return *reinterpret_cast<uint32_t*>(&t);
}
__device__ __forceinline__ uint32_t smem_u32addr(const void* p) {
    uint32_t a;
    asm("{ .reg .u64 t; cvta.to.shared.u64 t, %1; cvt.u32.u64 %0, t; }"
        : "=r"(a) : "l"(p));
    return a;
}
__device__ __forceinline__ void ldmx4(uint32_t& r0, uint32_t& r1,
                                      uint32_t& r2, uint32_t& r3,
                                      uint32_t addr) {
    asm volatile(
        "ldmatrix.sync.aligned.m8n8.x4.shared.b16 {%0,%1,%2,%3}, [%4];"
        : "=r"(r0), "=r"(r1), "=r"(r2), "=r"(r3) : "r"(addr));
}
__device__ __forceinline__ void ldmx4t(uint32_t& r0, uint32_t& r1,
                                       uint32_t& r2, uint32_t& r3,
                                       uint32_t addr) {
    asm volatile(
        "ldmatrix.sync.aligned.m8n8.x4.trans.shared.b16 {%0,%1,%2,%3}, [%4];"
        : "=r"(r0), "=r"(r1), "=r"(r2), "=r"(r3) : "r"(addr));
}
__device__ __forceinline__ void cp16(uint32_t dst, const void* src) {
    asm volatile("cp.async.cg.shared.global [%0], [%1], 16;"
                 :: "r"(dst), "l"(src) : "memory");
}
#define CP_COMMIT() asm volatile("cp.async.commit_group;" ::: "memory")
#define CP_WAIT0()  asm volatile("cp.async.wait_group 0;" ::: "memory")
#define CP_WAIT1()  asm volatile("cp.async.wait_group 1;" ::: "memory")

__device__ __forceinline__ void split4(float4 v, uint32_t& h0, uint32_t& h1,
                                       uint32_t& l0, uint32_t& l1) {
    __nv_bfloat16 hx = __float2bfloat16_rn(v.x);
    __nv_bfloat16 hy = __float2bfloat16_rn(v.y);
    __nv_bfloat16 hz = __float2bfloat16_rn(v.z);
    __nv_bfloat16 hw = __float2bfloat16_rn(v.w);
    h0 = pack2(hx, hy); h1 = pack2(hz, hw);
    l0 = pack2(__float2bfloat16_rn(v.x - __bfloat162float(hx)),
               __float2bfloat16_rn(v.y - __bfloat162float(hy)));
    l1 = pack2(__float2bfloat16_rn(v.z - __bfloat162float(hz)),
               __float2bfloat16_rn(v.w - __bfloat162float(hw)));
}
// split 2 floats -> (hi u32, lo u32)
__device__ __forceinline__ void split2(float a, float b, uint32_t& h, uint32_t& l) {
    __nv_bfloat16 ha = __float2bfloat16_rn(a);
    __nv_bfloat16 hb = __float2bfloat16_rn(b);
    h = pack2(ha, hb);
    l = pack2(__float2bfloat16_rn(a - __bfloat162float(ha)),
              __float2bfloat16_rn(b - __bfloat162float(hb)));
}

// ===========================================================================
// Trig table: 65536 (l, i) angles computed once per launch in fp64 —
// identical arithmetic to the former per-element path.
// ===========================================================================
__global__ __launch_bounds__(256) void trig_kernel(float2* __restrict__ trig) {
    int idx = blockIdx.x * 256 + threadIdx.x;
    int l = idx >> 5, i = idx & 31;
    double inv = pow(10000.0, -(double)i / 32.0);
    double ang = (double)l * inv;
    double snd, csd;
    sincos(ang, &snd, &csd);
    trig[idx] = make_float2((float)csd, (float)snd);
}

// ===========================================================================
// LayerNorm: one block per row, writes bf16 hi/lo split directly
// ===========================================================================
__global__ __launch_bounds__(256) void ln_kernel(const float* __restrict__ x,
                                                 __nv_bfloat16* __restrict__ hh,
                                                 __nv_bfloat16* __restrict__ hl) {
    int row = blockIdx.x;
    int t = threadIdx.x;
    const float4* xr = (const float4*)(x + (size_t)row * DM);
    float4 v = xr[t];
    float s  = v.x + v.y + v.z + v.w;
    float ss = v.x * v.x + v.y * v.y + v.z * v.z + v.w * v.w;
    #pragma unroll
    for (int off = 16; off; off >>= 1) {
        s  += __shfl_xor_sync(0xffffffffu, s, off);
        ss += __shfl_xor_sync(0xffffffffu, ss, off);
    }
    __shared__ float sh[16];
    __shared__ float sh_mu, sh_r;
    int warp = t >> 5, lane = t & 31;
    if (lane == 0) { sh[warp] = s; sh[warp + 8] = ss; }
    __syncthreads();
    if (t == 0) {
        float S = 0.f, SS = 0.f;
        #pragma unroll
        for (int w = 0; w < 8; w++) { S += sh[w]; SS += sh[w + 8]; }
        float mu  = S * (1.0f / DM);
        float var = SS * (1.0f / DM) - mu * mu;
        sh_mu = mu;
        sh_r  = rsqrtf(var + 1e-8f);
    }
    __syncthreads();
    float mu = sh_mu, r = sh_r;
    float4 o = make_float4((v.x - mu) * r, (v.y - mu) * r,
                           (v.z - mu) * r, (v.w - mu) * r);
    uint32_t h0, h1, l0, l1;
    split4(o, h0, h1, l0, l1);
    uint32_t* hw = (uint32_t*)(hh + (size_t)row * DM);
    uint32_t* lw = (uint32_t*)(hl + (size_t)row * DM);
    hw[2 * t] = h0; hw[2 * t + 1] = h1;
    lw[2 * t] = l0; lw[2 * t + 1] = l1;
}

// ===========================================================================
// Weight split: fp32 -> bf16 hi/lo
// ===========================================================================
__global__ __launch_bounds__(256) void split_kernel(const float* __restrict__ src,
                                                    __nv_bfloat16* __restrict__ hi,
                                                    __nv_bfloat16* __restrict__ lo,
                                                    int n4) {
    int i = blockIdx.x * blockDim.x + threadIdx.x;
    if (i >= n4) return;
    float4 v = ((const float4*)src)[i];
    uint32_t h0, h1, l0, l1;
    split4(v, h0, h1, l0, l1);
    ((uint32_t*)hi)[2 * i] = h0; ((uint32_t*)hi)[2 * i + 1] = h1;
    ((uint32_t*)lo)[2 * i] = l0; ((uint32_t*)lo)[2 * i + 1] = l1;
}

// ===========================================================================
// RoPE + split: table-driven trig; apply rope to q,k; split q/k/v hi/lo.
// ===========================================================================
__global__ __launch_bounds__(512) void rope_split(const float* __restrict__ qkv,
        const float2* __restrict__ trig,
        __nv_bfloat16* __restrict__ qh, __nv_bfloat16* __restrict__ ql,
        __nv_bfloat16* __restrict__ kh, __nv_bfloat16* __restrict__ kl,
        __nv_bfloat16* __restrict__ vh, __nv_bfloat16* __restrict__ vl) {
    int token = blockIdx.x;
    int p = threadIdx.x;
    int head = p >> 5;
    int i = p & 31;
    int l = token & (LSEQ - 1);
    float2 cssn = trig[l * 32 + i];
    float cs = cssn.x, sn = cssn.y;
    size_t base = (size_t)token * 3 * DM + head * DK + 2 * i;
    size_t di = ((size_t)token * DM + head * DK + 2 * i) >> 1;  // u32 index
    uint32_t h, lo;
    float x1 = qkv[base], x2 = qkv[base + 1];
    split2(x1 * cs - x2 * sn, x1 * sn + x2 * cs, h, lo);
    ((uint32_t*)qh)[di] = h; ((uint32_t*)ql)[di] = lo;
    float y1 = qkv[base + DM], y2 = qkv[base + DM + 1];
    split2(y1 * cs - y2 * sn, y1 * sn + y2 * cs, h, lo);
    ((uint32_t*)kh)[di] = h; ((uint32_t*)kl)[di] = lo;
    split2(qkv[base + 2 * DM], qkv[base + 2 * DM + 1], h, lo);
    ((uint32_t*)vh)[di] = h; ((uint32_t*)vl)[di] = lo;
}

// ===========================================================================
// Split-bf16 NT GEMM — 128 threads (4 warps, 2x2 grid, warp tile 64x64),
// 128x128 CTA tile, 2-stage cp.async, 2 CTAs/SM.
// ===========================================================================
#define BM 128
#define BN 128
#define SROW 12
#define SARR (BM * SROW)              // 1536 u32
#define SSTAGE (4 * SARR)
#define GEMM_SMEM (2 * SSTAGE * 4)    // 49152 B

__global__ __launch_bounds__(128, 2) void gemm_bf(
    const __nv_bfloat16* __restrict__ Ah, const __nv_bfloat16* __restrict__ Al,
    const __nv_bfloat16* __restrict__ Bh, const __nv_bfloat16* __restrict__ Bl,
    float* __restrict__ C, int M, int N_, int K) {
    extern __shared__ uint32_t smu[];
    int t = threadIdx.x;
    int lane = t & 31, wid = t >> 5;
    int wm = wid >> 1, wn = wid & 1;      // 2 x 2 warp grid, 64x64 tiles
    int g = lane >> 2, t4 = lane & 3;
    int m0 = blockIdx.y * BM, n0 = blockIdx.x * BN;

    float acc[4][8][4];
    #pragma unroll
    for (int i = 0; i < 4; i++)
        #pragma unroll
        for (int j = 0; j < 8; j++)
            #pragma unroll
            for (int q = 0; q < 4; q++) acc[i][j][q] = 0.f;

    int lrow = t >> 1, lhalf = t & 1;
    uint32_t sbase = smem_u32addr(smu);
    uint32_t so0 = (lrow * SROW + lhalf * 4) * 4;
    uint32_t so1 = ((lrow + 64) * SROW + lhalf * 4) * 4;
    const __nv_bfloat16* ap  = Ah + (size_t)(m0 + lrow) * K + lhalf * 8;
    const __nv_bfloat16* alp = Al + (size_t)(m0 + lrow) * K + lhalf * 8;
    const __nv_bfloat16* bp  = Bh + (size_t)(n0 + lrow) * K + lhalf * 8;
    const __nv_bfloat16* blp = Bl + (size_t)(n0 + lrow) * K + lhalf * 8;
    const size_t r64 = (size_t)64 * K;

    const int NST = K / 16;
    cp16(sbase + so0,                ap);
    cp16(sbase + so1,                ap + r64);
    cp16(sbase + SARR * 4 + so0,     alp);
    cp16(sbase + SARR * 4 + so1,     alp + r64);
    cp16(sbase + 2 * SARR * 4 + so0, bp);
    cp16(sbase + 2 * SARR * 4 + so1, bp + r64);
    cp16(sbase + 3 * SARR * 4 + so0, blp);
    cp16(sbase + 3 * SARR * 4 + so1, blp + r64);
    CP_COMMIT();

    int r8 = lane & 7, mat = lane >> 3;
    int a_loff = ((wm * 64 + (mat & 1) * 8 + r8) * SROW + (mat >> 1) * 4) * 4;
    int b_loff = ((wn * 64 + (mat >> 1) * 8 + r8) * SROW + (mat & 1) * 4) * 4;

    for (int s = 0; s < NST; s++) {
        CP_WAIT0();
        __syncthreads();
        if (s + 1 < NST) {
            int k0 = (s + 1) * 16;
            uint32_t db = sbase + ((s + 1) & 1) * (SSTAGE * 4);
            cp16(db + so0,                ap + k0);
            cp16(db + so1,                ap + r64 + k0);
            cp16(db + SARR * 4 + so0,     alp + k0);
            cp16(db + SARR * 4 + so1,     alp + r64 + k0);
            cp16(db + 2 * SARR * 4 + so0, bp + k0);
            cp16(db + 2 * SARR * 4 + so1, bp + r64 + k0);
            cp16(db + 3 * SARR * 4 + so0, blp + k0);
            cp16(db + 3 * SARR * 4 + so1, blp + r64 + k0);
            CP_COMMIT();
        }

        uint32_t stb = sbase + (s & 1) * (SSTAGE * 4);
        uint32_t bh[8][2], bl[8][2];
        #pragma unroll
        for (int p = 0; p < 4; p++) {
            ldmx4(bh[2 * p][0], bh[2 * p][1], bh[2 * p + 1][0], bh[2 * p + 1][1],
                  stb + 2 * SARR * 4 + b_loff + p * (16 * SROW * 4));
            ldmx4(bl[2 * p][0], bl[2 * p][1], bl[2 * p + 1][0], bl[2 * p + 1][1],
                  stb + 3 * SARR * 4 + b_loff + p * (16 * SROW * 4));
        }
        #pragma unroll
        for (int mb = 0; mb < 4; mb++) {
            uint32_t ah[4], al[4];
            ldmx4(ah[0], ah[1], ah[2], ah[3],
                  stb + a_loff + mb * (16 * SROW * 4));
            ldmx4(al[0], al[1], al[2], al[3],
                  stb + SARR * 4 + a_loff + mb * (16 * SROW * 4));
            #pragma unroll
            for (int nb = 0; nb < 8; nb++) {
                mma_bf16(acc[mb][nb], ah, bh[nb]);
                mma_bf16(acc[mb][nb], ah, bl[nb]);
                mma_bf16(acc[mb][nb], al, bh[nb]);
            }
        }
    }

    #pragma unroll
    for (int mb = 0; mb < 4; mb++) {
        int row = m0 + wm * 64 + mb * 16 + g;
        #pragma unroll
        for (int nb = 0; nb < 8; nb++) {
            int col = n0 + wn * 64 + nb * 8 + 2 * t4;
            *(float2*)(C + (size_t)row * N_ + col) =
                make_float2(acc[mb][nb][0], acc[mb][nb][1]);
            *(float2*)(C + (size_t)(row + 8) * N_ + col) =
                make_float2(acc[mb][nb][2], acc[mb][nb][3]);
        }
    }
}

// ===========================================================================
// Tensor-core causal flash attention. Pre-split bf16 inputs, cp.async
// staging, double-buffered K/V tiles. Epilogue writes bf16 hi/lo.
// ===========================================================================
#define FQ 128
#define FK 64
#define FR 36                          // u32 row stride (144 B)
#define OQH 0
#define OQL (FQ * FR)                  // 4608
#define KV0 (2 * FQ * FR)              // 9216
#define SST (4 * FK * FR)              // 9216 u32 per stage
#define KH_O 0
#define KL_O (FK * FR)                 // 2304
#define VH_O (2 * FK * FR)
#define VL_O (3 * FK * FR)
#define FLASH_SMEM ((KV0 + 2 * SST) * 4)   // 110592 B

__global__ __launch_bounds__(256) void flash_tc(
        const __nv_bfloat16* __restrict__ qhp, const __nv_bfloat16* __restrict__ qlp,
        const __nv_bfloat16* __restrict__ khp, const __nv_bfloat16* __restrict__ klp,
        const __nv_bfloat16* __restrict__ vhp, const __nv_bfloat16* __restrict__ vlp,
        __nv_bfloat16* __restrict__ oh, __nv_bfloat16* __restrict__ ol) {
    extern __shared__ uint32_t su[];
    int t = threadIdx.x;
    int lane = t & 31, wq = t >> 5;
    int g = lane >> 2, t4 = lane & 3;
    int qt = (int)gridDim.x - 1 - (int)blockIdx.x;
    int h = blockIdx.y, b = blockIdx.z;
    int qbase = qt * FQ;
    uint32_t sbase = smem_u32addr(su);

    // ---- Q staging via cp.async (group 0) ----
    {
        size_t qoff = (size_t)(b * LSEQ + qbase) * DM + h * DK;
        #pragma unroll
        for (int it = 0; it < 4; it++) {
            int f = t + it * 256;           // 0..1023
            int row = f >> 3, c = f & 7;
            uint32_t d = sbase + row * 144 + c * 16;
            cp16(d,           qhp + qoff + (size_t)row * DM + c * 8);
            cp16(d + OQL * 4, qlp + qoff + (size_t)row * DM + c * 8);
        }
        CP_COMMIT();
    }
    // ---- K/V tile 0 staging (group 1) ----
    int nkt = 2 * qt + 2;
    {
        size_t koff = (size_t)(b * LSEQ) * DM + h * DK;
        #pragma unroll
        for (int it = 0; it < 2; it++) {
            int f = t + it * 256;           // 0..511
            int row = f >> 3, c = f & 7;
            uint32_t d = sbase + KV0 * 4 + row * 144 + c * 16;
            size_t s = koff + (size_t)row * DM + c * 8;
            cp16(d,            khp + s);
            cp16(d + KL_O * 4, klp + s);
            cp16(d + VH_O * 4, vhp + s);
            cp16(d + VL_O * 4, vlp + s);
        }
        CP_COMMIT();
    }
    CP_WAIT1();                 // Q done
    __syncthreads();

    uint32_t qah[4][4], qal[4][4];
    #pragma unroll
    for (int s = 0; s < 4; s++) {
        int idx = (wq * 16 + g) * FR + 8 * s + t4;
        qah[s][0] = su[OQH + idx];          qah[s][1] = su[OQH + idx + 8 * FR];
        qah[s][2] = su[OQH + idx + 4];      qah[s][3] = su[OQH + idx + 8 * FR + 4];
        qal[s][0] = su[OQL + idx];          qal[s][1] = su[OQL + idx + 8 * FR];
        qal[s][2] = su[OQL + idx + 4];      qal[s][3] = su[OQL + idx + 8 * FR + 4];
    }

    float of[8][4];
    #pragma unroll
    for (int n = 0; n < 8; n++)
        #pragma unroll
        for (int c = 0; c < 4; c++) of[n][c] = 0.f;
    float m0 = -1e30f, m1 = -1e30f, l0 = 0.f, l1 = 0.f;

    int voff = ((lane & 15) * FR + (lane >> 4) * 4) * 4;
    int row0 = qbase + wq * 16 + g;

    for (int kt = 0; kt < nkt; kt++) {
        CP_WAIT0();             // tile kt staged
        __syncthreads();
        int st = kt & 1;
        if (kt + 1 < nkt) {
            size_t koff = (size_t)(b * LSEQ + (kt + 1) * FK) * DM + h * DK;
            uint32_t dbase = sbase + (KV0 + (1 - st) * SST) * 4;
            #pragma unroll
            for (int it = 0; it < 2; it++) {
                int f = t + it * 256;
                int row = f >> 3, c = f & 7;
                uint32_t d = dbase + row * 144 + c * 16;
                size_t s = koff + (size_t)row * DM + c * 8;
                cp16(d,            khp + s);
                cp16(d + KL_O * 4, klp + s);
                cp16(d + VH_O * 4, vhp + s);
                cp16(d + VL_O * 4, vlp + s);
            }
        }
        CP_COMMIT();

        int ktb = kt * FK;
        bool active = (ktb <= qbase + wq * 16);
        if (active) {
            const uint32_t* stK = su + KV0 + st * SST;
            uint32_t vb_h = sbase + (KV0 + st * SST + VH_O) * 4;
            uint32_t vb_l = sbase + (KV0 + st * SST + VL_O) * 4;

            float sf[8][4];
            #pragma unroll
            for (int j = 0; j < 8; j++)
                #pragma unroll
                for (int c = 0; c < 4; c++) sf[j][c] = 0.f;
            #pragma unroll
            for (int s = 0; s < 4; s++) {
                #pragma unroll
                for (int j = 0; j < 8; j++) {
                    int idx = (8 * j + g) * FR + 8 * s + t4;
                    uint32_t kb2[2], kl2[2];
                    kb2[0] = stK[KH_O + idx]; kb2[1] = stK[KH_O + idx + 4];
                    kl2[0] = stK[KL_O + idx]; kl2[1] = stK[KL_O + idx + 4];
                    mma_bf16(sf[j], qah[s], kb2);
                    mma_bf16(sf[j], qal[s], kb2);
                    mma_bf16(sf[j], qah[s], kl2);
                }
            }

            const float scale = 0.125f;
            bool need_mask = (ktb + FK - 1 > qbase + wq * 16);
            #pragma unroll
            for (int j = 0; j < 8; j++) {
                int col = ktb + 8 * j + 2 * t4;
                #pragma unroll
                for (int c = 0; c < 4; c++) {
                    float v = sf[j][c] * scale;
                    if (need_mask) {
                        int cc = col + (c & 1);
                        int rr = row0 + (c >> 1) * 8;
                        if (cc > rr) v = -1e30f;
                    }
                    sf[j][c] = v;
                }
            }

            float mx0 = -1e30f, mx1 = -1e30f;
            #pragma unroll
            for (int j = 0; j < 8; j++) {
                mx0 = fmaxf(mx0, fmaxf(sf[j][0], sf[j][1]));
                mx1 = fmaxf(mx1, fmaxf(sf[j][2], sf[j][3]));
            }
            mx0 = fmaxf(mx0, __shfl_xor_sync(0xffffffffu, mx0, 1));
            mx0 = fmaxf(mx0, __shfl_xor_sync(0xffffffffu, mx0, 2));
            mx1 = fmaxf(mx1, __shfl_xor_sync(0xffffffffu, mx1, 1));
            mx1 = fmaxf(mx1, __shfl_xor_sync(0xffffffffu, mx1, 2));
            float mn0 = fmaxf(m0, mx0), mn1 = fmaxf(m1, mx1);
            float a0 = __expf(m0 - mn0), a1 = __expf(m1 - mn1);
            m0 = mn0; m1 = mn1;
            float s0 = 0.f, s1 = 0.f;
            #pragma unroll
            for (int j = 0; j < 8; j++) {
                sf[j][0] = __expf(sf[j][0] - m0);
                sf[j][1] = __expf(sf[j][1] - m0);
                sf[j][2] = __expf(sf[j][2] - m1);
                sf[j][3] = __expf(sf[j][3] - m1);
                s0 += sf[j][0] + sf[j][1];
                s1 += sf[j][2] + sf[j][3];
            }
            s0 += __shfl_xor_sync(0xffffffffu, s0, 1);
            s0 += __shfl_xor_sync(0xffffffffu, s0, 2);
            s1 += __shfl_xor_sync(0xffffffffu, s1, 1);
            s1 += __shfl_xor_sync(0xffffffffu, s1, 2);
            l0 = l0 * a0 + s0;
            l1 = l1 * a1 + s1;
            #pragma unroll
            for (int n = 0; n < 8; n++) {
                of[n][0] *= a0; of[n][1] *= a0;
                of[n][2] *= a1; of[n][3] *= a1;
            }

            #pragma unroll
            for (int s = 0; s < 4; s++) {
                uint32_t pah[4], pal[4];
                #pragma unroll
                for (int half = 0; half < 2; half++) {
                    float p0 = sf[2 * s + half][0], p1 = sf[2 * s + half][1];
                    float p2 = sf[2 * s + half][2], p3 = sf[2 * s + half][3];
                    split2(p0, p1, pah[2 * half], pal[2 * half]);
                    split2(p2, p3, pah[2 * half + 1], pal[2 * half + 1]);
                }
                #pragma unroll
                for (int j2 = 0; j2 < 4; j2++) {
                    uint32_t vh0, vh1, vh2, vh3, vl0, vl1, vl2, vl3;
                    uint32_t boff2 = (16 * s * FR + 8 * j2) * 4 + voff;
                    ldmx4t(vh0, vh1, vh2, vh3, vb_h + boff2);
                    ldmx4t(vl0, vl1, vl2, vl3, vb_l + boff2);
                    uint32_t bh0[2] = {vh0, vh1}, bh1[2] = {vh2, vh3};
                    uint32_t bl0[2] = {vl0, vl1}, bl1[2] = {vl2, vl3};
                    mma_bf16(of[2 * j2], pah, bh0);
                    mma_bf16(of[2 * j2], pal, bh0);
                    mma_bf16(of[2 * j2], pah, bl0);
                    mma_bf16(of[2 * j2 + 1], pah, bh1);
                    mma_bf16(of[2 * j2 + 1], pal, bh1);
                    mma_bf16(of[2 * j2 + 1], pah, bl1);
                }
            }
        }
        __syncthreads();
    }

    // ---- epilogue: write bf16 hi/lo split ----
    float i0 = 1.f / l0, i1 = 1.f / l1;
    size_t base0 = (size_t)(b * LSEQ + row0) * DM + h * DK;
    size_t base1 = base0 + 8 * DM;
    uint32_t* ohw = (uint32_t*)oh;
    uint32_t* olw = (uint32_t*)ol;
    #pragma unroll
    for (int n = 0; n < 8; n++) {
        int col = 8 * n + 2 * t4;
        uint32_t h0, l0w, h1, l1w;
        split2(of[n][0] * i0, of[n][1] * i0, h0, l0w);
        split2(of[n][2] * i1, of[n][3] * i1, h1, l1w);
        ohw[(base0 + col) >> 1] = h0;
        olw[(base0 + col) >> 1] = l0w;
        ohw[(base1 + col) >> 1] = h1;
        olw[(base1 + col) >> 1] = l1w;
    }
}

// ===========================================================================
extern "C" void kernel_launch(void* const* d_in, const int* in_sizes, int n_in,
                              void* d_out, int out_size) {
    const float* x    = (const float*)d_in[0];
    const float* W_in = (const float*)d_in[1];
    const float* W_o  = (const float*)d_in[2];
    float* out = (float*)d_out;

    float* qkv;
    float2* trig;
    __nv_bfloat16 *hh, *hl, *wih, *wil, *woh, *wol, *oh, *ol;
    __nv_bfloat16 *qh, *ql, *kh, *kl, *vh, *vl;
    cudaGetSymbolAddress((void**)&qkv, g_qkv);
    cudaGetSymbolAddress((void**)&trig, g_trig);
    cudaGetSymbolAddress((void**)&hh,  g_hh);
    cudaGetSymbolAddress((void**)&hl,  g_hl);
    cudaGetSymbolAddress((void**)&wih, g_wih);
    cudaGetSymbolAddress((void**)&wil, g_wil);
    cudaGetSymbolAddress((void**)&woh, g_woh);
    cudaGetSymbolAddress((void**)&wol, g_wol);
    cudaGetSymbolAddress((void**)&oh,  g_oh);
    cudaGetSymbolAddress((void**)&ol,  g_ol);
    cudaGetSymbolAddress((void**)&qh,  g_qh);
    cudaGetSymbolAddress((void**)&ql,  g_ql);
    cudaGetSymbolAddress((void**)&kh,  g_kh);
    cudaGetSymbolAddress((void**)&kl,  g_kl);
    cudaGetSymbolAddress((void**)&vh,  g_vh);
    cudaGetSymbolAddress((void**)&vl,  g_vl);

    cudaFuncSetAttribute(gemm_bf, cudaFuncAttributeMaxDynamicSharedMemorySize,
                         GEMM_SMEM);
    cudaFuncSetAttribute(flash_tc, cudaFuncAttributeMaxDynamicSharedMemorySize,
                         FLASH_SMEM);

    trig_kernel<<<LSEQ * 32 / 256, 256>>>(trig);
    ln_kernel<<<TOKENS, 256>>>(x, hh, hl);
    split_kernel<<<(3 * DM * DM / 4 + 255) / 256, 256>>>(W_in, wih, wil,
                                                         3 * DM * DM / 4);
    split_kernel<<<(DM * DM / 4 + 255) / 256, 256>>>(W_o, woh, wol,
                                                     DM * DM / 4);

    dim3 g1(3 * DM / BN, TOKENS / BM);
    gemm_bf<<<g1, 128, GEMM_SMEM>>>(hh, hl, wih, wil, qkv, TOKENS, 3 * DM, DM);

    rope_split<<<TOKENS, 512>>>(qkv, trig, qh, ql, kh, kl, vh, vl);

    dim3 g2(LSEQ / FQ, NH, NB);
    flash_tc<<<g2, 256, FLASH_SMEM>>>(qh, ql, kh, kl, vh, vl, oh, ol);

    dim3 g3(DM / BN, TOKENS / BM);
    gemm_bf<<<g3, 128, GEMM_SMEM>>>(oh, ol, woh, wol, out, TOKENS, DM, DM);
}